// round 1
// baseline (speedup 1.0000x reference)
#include <cuda_runtime.h>
#include <cuda_bf16.h>
#include <cstdint>

// Problem constants
#define BB 4
#define SS 2048
#define EE 1024
#define DD 64
#define MTOT (BB * SS)   // 8192

// Scratch: Q and K stored TRANSPOSED per batch: [b][d][s]; V row-major [b][s][d]
__device__ float g_qt[BB * DD * SS];
__device__ float g_kt[BB * DD * SS];
__device__ float g_v [BB * SS * DD];

// ---------------------------------------------------------------------------
// Kernel 1: fused QKV projection.
//   mode 0: q = x @ Wk + bk   (reference swaps K/Q projections)  -> g_qt (transposed)
//   mode 1: k = x @ Wq + bq                                      -> g_kt (transposed)
//   mode 2: v = x @ Wv + bv                                      -> g_v  (row-major)
// Tile: 64 (M) x 64 (N=D) x 32 (K). 256 threads, 4x4 fragment each.
// ---------------------------------------------------------------------------
__global__ __launch_bounds__(256) void proj_kernel(
    const float* __restrict__ x,
    const float* __restrict__ Wq, const float* __restrict__ bq,
    const float* __restrict__ Wk, const float* __restrict__ bk,
    const float* __restrict__ Wv, const float* __restrict__ bv)
{
    __shared__ __align__(16) float Xs[64][36];  // 64 rows x 32 (+4 pad)
    __shared__ __align__(16) float Ws[32][64];

    const float *W, *bias;
    const int mode = blockIdx.y;
    if (mode == 0)      { W = Wk; bias = bk; }
    else if (mode == 1) { W = Wq; bias = bq; }
    else                { W = Wv; bias = bv; }

    const int tid = threadIdx.x;
    const int ty = tid >> 4;      // 0..15 -> rows ty*4..ty*4+3
    const int tx = tid & 15;      // 0..15 -> cols tx*4..tx*4+3
    const int m0 = blockIdx.x * 64;

    float acc[4][4] = {};

    for (int k0 = 0; k0 < EE; k0 += 32) {
        // Load X tile 64x32 (512 float4s, 2 per thread)
        #pragma unroll
        for (int i = 0; i < 2; i++) {
            int idx = tid + i * 256;
            int r  = idx >> 3;        // 8 float4 per row of 32
            int c4 = idx & 7;
            *(float4*)&Xs[r][c4 * 4] =
                *(const float4*)&x[(size_t)(m0 + r) * EE + k0 + c4 * 4];
            int r2  = idx >> 4;       // 16 float4 per row of 64
            int c42 = idx & 15;
            *(float4*)&Ws[r2][c42 * 4] =
                *(const float4*)&W[(size_t)(k0 + r2) * DD + c42 * 4];
        }
        __syncthreads();

        #pragma unroll
        for (int kk = 0; kk < 32; kk++) {
            float a[4];
            #pragma unroll
            for (int r = 0; r < 4; r++) a[r] = Xs[ty * 4 + r][kk];
            float4 b4 = *(const float4*)&Ws[kk][tx * 4];
            float bb[4] = {b4.x, b4.y, b4.z, b4.w};
            #pragma unroll
            for (int r = 0; r < 4; r++)
                #pragma unroll
                for (int c = 0; c < 4; c++)
                    acc[r][c] += a[r] * bb[c];
        }
        __syncthreads();
    }

    float4 bvec = *(const float4*)&bias[tx * 4];
    float bb[4] = {bvec.x, bvec.y, bvec.z, bvec.w};

    if (mode == 2) {
        // row-major store [b][s][d]  == flat [m][d]
        #pragma unroll
        for (int r = 0; r < 4; r++) {
            float4 o4 = make_float4(acc[r][0] + bb[0], acc[r][1] + bb[1],
                                    acc[r][2] + bb[2], acc[r][3] + bb[3]);
            *(float4*)&g_v[(size_t)(m0 + ty * 4 + r) * DD + tx * 4] = o4;
        }
    } else {
        // transposed store [b][d][s]
        float* out = (mode == 0) ? g_qt : g_kt;
        #pragma unroll
        for (int r = 0; r < 4; r++) {
            int s  = m0 + ty * 4 + r;
            int bi = s >> 11;          // / 2048
            int si = s & (SS - 1);
            #pragma unroll
            for (int c = 0; c < 4; c++)
                out[((size_t)bi * DD + tx * 4 + c) * SS + si] = acc[r][c] + bb[c];
        }
    }
}

// ---------------------------------------------------------------------------
// Kernel 2: fp32 causal flash attention.
// Grid: (S/64, B). 256 threads. Each CTA: 64 queries, streams KV tiles of 64.
// Smem (48KB exactly): QsT[d][i], KP[*][*] (K^T tile, then reused as P^T tile),
// Vs[j][d]. All compute-phase accesses are broadcast or lane-consecutive float4.
// ---------------------------------------------------------------------------
__global__ __launch_bounds__(256) void flash_kernel(float* __restrict__ out)
{
    __shared__ __align__(16) float QsT[64][64];  // QsT[d][i]
    __shared__ __align__(16) float KP [64][64];  // Kt[d][j]  then  PsT[j][i]
    __shared__ __align__(16) float Vs [64][64];  // Vs[j][d]

    const int tid = threadIdx.x;
    const int ty = tid >> 4;     // query rows ty*4..+3
    const int tx = tid & 15;     // key cols / d cols tx*4..+3
    const int qt = blockIdx.x;
    const int b  = blockIdx.y;
    const int q0 = qt * 64;

    const float* qtb = g_qt + (size_t)b * DD * SS;
    const float* ktb = g_kt + (size_t)b * DD * SS;
    const float* vb  = g_v  + (size_t)b * SS * DD;

    // Load Q^T tile: QsT[d][i] = qt[d][q0+i]
    #pragma unroll
    for (int i = 0; i < 4; i++) {
        int idx = tid + i * 256;
        int r = idx >> 4, c4 = idx & 15;
        *(float4*)&QsT[r][c4 * 4] =
            *(const float4*)&qtb[(size_t)r * SS + q0 + c4 * 4];
    }

    float m[4], l[4], o[4][4];
    #pragma unroll
    for (int r = 0; r < 4; r++) {
        m[r] = -1e30f; l[r] = 0.f;
        #pragma unroll
        for (int c = 0; c < 4; c++) o[r][c] = 0.f;
    }
    const float scale = 0.125f;  // 1/sqrt(64)

    for (int kti = 0; kti <= qt; kti++) {
        const int k0 = kti * 64;
        __syncthreads();  // previous-iteration readers done

        // Load K^T and V tiles
        #pragma unroll
        for (int i = 0; i < 4; i++) {
            int idx = tid + i * 256;
            int r = idx >> 4, c4 = idx & 15;
            *(float4*)&KP[r][c4 * 4] =
                *(const float4*)&ktb[(size_t)r * SS + k0 + c4 * 4];
            *(float4*)&Vs[r][c4 * 4] =
                *(const float4*)&vb[(size_t)(k0 + r) * DD + c4 * 4];
        }
        __syncthreads();

        // S = Q K^T   (s[r][c] : query q0+ty*4+r, key k0+tx*4+c)
        float s[4][4] = {};
        #pragma unroll 8
        for (int d = 0; d < 64; d++) {
            float4 a4 = *(const float4*)&QsT[d][ty * 4];
            float4 k4 = *(const float4*)&KP[d][tx * 4];
            float a[4]  = {a4.x, a4.y, a4.z, a4.w};
            float kk[4] = {k4.x, k4.y, k4.z, k4.w};
            #pragma unroll
            for (int r = 0; r < 4; r++)
                #pragma unroll
                for (int c = 0; c < 4; c++)
                    s[r][c] += a[r] * kk[c];
        }

        // scale + causal mask (only the diagonal tile needs masking)
        const bool diag = (kti == qt);
        #pragma unroll
        for (int r = 0; r < 4; r++) {
            int ig = q0 + ty * 4 + r;
            #pragma unroll
            for (int c = 0; c < 4; c++) {
                float v = s[r][c] * scale;
                if (diag && (k0 + tx * 4 + c) > ig) v = -1e30f;
                s[r][c] = v;
            }
        }

        // online softmax: rows are shared by the 16 tx-lanes (xor bits 0..3)
        #pragma unroll
        for (int r = 0; r < 4; r++) {
            float pm = fmaxf(fmaxf(s[r][0], s[r][1]), fmaxf(s[r][2], s[r][3]));
            #pragma unroll
            for (int off = 8; off >= 1; off >>= 1)
                pm = fmaxf(pm, __shfl_xor_sync(0xffffffffu, pm, off));
            float mnew = fmaxf(m[r], pm);
            float corr = __expf(m[r] - mnew);
            m[r] = mnew;
            float rs = 0.f;
            #pragma unroll
            for (int c = 0; c < 4; c++) {
                float p = __expf(s[r][c] - mnew);
                s[r][c] = p;
                rs += p;
            }
            #pragma unroll
            for (int off = 8; off >= 1; off >>= 1)
                rs += __shfl_xor_sync(0xffffffffu, rs, off);
            l[r] = l[r] * corr + rs;
            #pragma unroll
            for (int c = 0; c < 4; c++) o[r][c] *= corr;
        }

        __syncthreads();  // everyone done reading KP as K^T
        // Write P^T into KP: KP[j][i] = P[i][j]
        #pragma unroll
        for (int c = 0; c < 4; c++)
            *(float4*)&KP[tx * 4 + c][ty * 4] =
                make_float4(s[0][c], s[1][c], s[2][c], s[3][c]);
        __syncthreads();

        // O += P @ V   (o[r][c] : query row, d col)
        #pragma unroll 8
        for (int j = 0; j < 64; j++) {
            float4 a4 = *(const float4*)&KP[j][ty * 4];
            float4 v4 = *(const float4*)&Vs[j][tx * 4];
            float a[4]  = {a4.x, a4.y, a4.z, a4.w};
            float vv[4] = {v4.x, v4.y, v4.z, v4.w};
            #pragma unroll
            for (int r = 0; r < 4; r++)
                #pragma unroll
                for (int c = 0; c < 4; c++)
                    o[r][c] += a[r] * vv[c];
        }
    }

    // epilogue: out[b][s][d] = O / l
    float* ob = out + (size_t)b * SS * DD;
    #pragma unroll
    for (int r = 0; r < 4; r++) {
        float inv = 1.0f / l[r];
        float4 o4 = make_float4(o[r][0] * inv, o[r][1] * inv,
                                o[r][2] * inv, o[r][3] * inv);
        *(float4*)&ob[(size_t)(q0 + ty * 4 + r) * DD + tx * 4] = o4;
    }
}

// ---------------------------------------------------------------------------
// Inputs (metadata order): x, mask, Wq, bq, Wk, bk, Wv, bv
// mask is the causal tril mask -> not read (causality hard-coded, exact).
// ---------------------------------------------------------------------------
extern "C" void kernel_launch(void* const* d_in, const int* in_sizes, int n_in,
                              void* d_out, int out_size)
{
    const float* x  = (const float*)d_in[0];
    const float* Wq = (const float*)d_in[2];
    const float* bq = (const float*)d_in[3];
    const float* Wk = (const float*)d_in[4];
    const float* bk = (const float*)d_in[5];
    const float* Wv = (const float*)d_in[6];
    const float* bv = (const float*)d_in[7];
    float* out = (float*)d_out;

    proj_kernel<<<dim3(MTOT / 64, 3), 256>>>(x, Wq, bq, Wk, bk, Wv, bv);
    flash_kernel<<<dim3(SS / 64, BB), 256>>>(out);
}

// round 2
// speedup vs baseline: 1.0057x; 1.0057x over previous
#include <cuda_runtime.h>
#include <cuda_bf16.h>
#include <cstdint>

// Problem constants
#define BB 4
#define SS 2048
#define EE 1024
#define DD 64
#define MTOT (BB * SS)   // 8192

// Scratch: Q and K stored TRANSPOSED per batch: [b][d][s]; V row-major [b][s][d]
__device__ float g_qt[BB * DD * SS];
__device__ float g_kt[BB * DD * SS];
__device__ float g_v [BB * SS * DD];

// ---------------------------------------------------------------------------
// Kernel 1: fused QKV projection.
//   mode 0: q = x @ Wk + bk   (reference swaps K/Q projections)  -> g_qt (transposed)
//   mode 1: k = x @ Wq + bq                                      -> g_kt (transposed)
//   mode 2: v = x @ Wv + bv                                      -> g_v  (row-major)
// Tile: 64 (M) x 64 (N=D) x 32 (K). 256 threads, 4x4 fragment each.
// ---------------------------------------------------------------------------
__global__ __launch_bounds__(256) void proj_kernel(
    const float* __restrict__ x,
    const float* __restrict__ Wq, const float* __restrict__ bq,
    const float* __restrict__ Wk, const float* __restrict__ bk,
    const float* __restrict__ Wv, const float* __restrict__ bv)
{
    __shared__ __align__(16) float Xs[64][36];  // 64 rows x 32 (+4 pad)
    __shared__ __align__(16) float Ws[32][64];

    const float *W, *bias;
    const int mode = blockIdx.y;
    if (mode == 0)      { W = Wk; bias = bk; }
    else if (mode == 1) { W = Wq; bias = bq; }
    else                { W = Wv; bias = bv; }

    const int tid = threadIdx.x;
    const int ty = tid >> 4;      // 0..15 -> rows ty*4..ty*4+3
    const int tx = tid & 15;      // 0..15 -> cols tx*4..tx*4+3
    const int m0 = blockIdx.x * 64;

    float acc[4][4] = {};

    for (int k0 = 0; k0 < EE; k0 += 32) {
        // Load X tile 64x32 (512 float4s, 2 per thread)
        #pragma unroll
        for (int i = 0; i < 2; i++) {
            int idx = tid + i * 256;
            int r  = idx >> 3;        // 8 float4 per row of 32
            int c4 = idx & 7;
            *(float4*)&Xs[r][c4 * 4] =
                *(const float4*)&x[(size_t)(m0 + r) * EE + k0 + c4 * 4];
            int r2  = idx >> 4;       // 16 float4 per row of 64
            int c42 = idx & 15;
            *(float4*)&Ws[r2][c42 * 4] =
                *(const float4*)&W[(size_t)(k0 + r2) * DD + c42 * 4];
        }
        __syncthreads();

        #pragma unroll
        for (int kk = 0; kk < 32; kk++) {
            float a[4];
            #pragma unroll
            for (int r = 0; r < 4; r++) a[r] = Xs[ty * 4 + r][kk];
            float4 b4 = *(const float4*)&Ws[kk][tx * 4];
            float bb[4] = {b4.x, b4.y, b4.z, b4.w};
            #pragma unroll
            for (int r = 0; r < 4; r++)
                #pragma unroll
                for (int c = 0; c < 4; c++)
                    acc[r][c] += a[r] * bb[c];
        }
        __syncthreads();
    }

    float4 bvec = *(const float4*)&bias[tx * 4];
    float bb[4] = {bvec.x, bvec.y, bvec.z, bvec.w};

    if (mode == 2) {
        // row-major store [b][s][d]  == flat [m][d]
        #pragma unroll
        for (int r = 0; r < 4; r++) {
            float4 o4 = make_float4(acc[r][0] + bb[0], acc[r][1] + bb[1],
                                    acc[r][2] + bb[2], acc[r][3] + bb[3]);
            *(float4*)&g_v[(size_t)(m0 + ty * 4 + r) * DD + tx * 4] = o4;
        }
    } else {
        // transposed store [b][d][s]
        float* out = (mode == 0) ? g_qt : g_kt;
        #pragma unroll
        for (int r = 0; r < 4; r++) {
            int s  = m0 + ty * 4 + r;
            int bi = s >> 11;          // / 2048
            int si = s & (SS - 1);
            #pragma unroll
            for (int c = 0; c < 4; c++)
                out[((size_t)bi * DD + tx * 4 + c) * SS + si] = acc[r][c] + bb[c];
        }
    }
}

// ---------------------------------------------------------------------------
// Kernel 2: fp32 causal flash attention.
// Grid: (S/64, B). 256 threads. Each CTA: 64 queries, streams KV tiles of 64.
// Smem (48KB exactly): QsT[d][i], KP[*][*] (K^T tile, then reused as P^T tile),
// Vs[j][d]. All compute-phase accesses are broadcast or lane-consecutive float4.
// ---------------------------------------------------------------------------
__global__ __launch_bounds__(256) void flash_kernel(float* __restrict__ out)
{
    __shared__ __align__(16) float QsT[64][64];  // QsT[d][i]
    __shared__ __align__(16) float KP [64][64];  // Kt[d][j]  then  PsT[j][i]
    __shared__ __align__(16) float Vs [64][64];  // Vs[j][d]

    const int tid = threadIdx.x;
    const int ty = tid >> 4;     // query rows ty*4..+3
    const int tx = tid & 15;     // key cols / d cols tx*4..+3
    const int qt = blockIdx.x;
    const int b  = blockIdx.y;
    const int q0 = qt * 64;

    const float* qtb = g_qt + (size_t)b * DD * SS;
    const float* ktb = g_kt + (size_t)b * DD * SS;
    const float* vb  = g_v  + (size_t)b * SS * DD;

    // Load Q^T tile: QsT[d][i] = qt[d][q0+i]
    #pragma unroll
    for (int i = 0; i < 4; i++) {
        int idx = tid + i * 256;
        int r = idx >> 4, c4 = idx & 15;
        *(float4*)&QsT[r][c4 * 4] =
            *(const float4*)&qtb[(size_t)r * SS + q0 + c4 * 4];
    }

    float m[4], l[4], o[4][4];
    #pragma unroll
    for (int r = 0; r < 4; r++) {
        m[r] = -1e30f; l[r] = 0.f;
        #pragma unroll
        for (int c = 0; c < 4; c++) o[r][c] = 0.f;
    }
    const float scale = 0.125f;  // 1/sqrt(64)

    for (int kti = 0; kti <= qt; kti++) {
        const int k0 = kti * 64;
        __syncthreads();  // previous-iteration readers done

        // Load K^T and V tiles
        #pragma unroll
        for (int i = 0; i < 4; i++) {
            int idx = tid + i * 256;
            int r = idx >> 4, c4 = idx & 15;
            *(float4*)&KP[r][c4 * 4] =
                *(const float4*)&ktb[(size_t)r * SS + k0 + c4 * 4];
            *(float4*)&Vs[r][c4 * 4] =
                *(const float4*)&vb[(size_t)(k0 + r) * DD + c4 * 4];
        }
        __syncthreads();

        // S = Q K^T   (s[r][c] : query q0+ty*4+r, key k0+tx*4+c)
        float s[4][4] = {};
        #pragma unroll 8
        for (int d = 0; d < 64; d++) {
            float4 a4 = *(const float4*)&QsT[d][ty * 4];
            float4 k4 = *(const float4*)&KP[d][tx * 4];
            float a[4]  = {a4.x, a4.y, a4.z, a4.w};
            float kk[4] = {k4.x, k4.y, k4.z, k4.w};
            #pragma unroll
            for (int r = 0; r < 4; r++)
                #pragma unroll
                for (int c = 0; c < 4; c++)
                    s[r][c] += a[r] * kk[c];
        }

        // scale + causal mask (only the diagonal tile needs masking)
        const bool diag = (kti == qt);
        #pragma unroll
        for (int r = 0; r < 4; r++) {
            int ig = q0 + ty * 4 + r;
            #pragma unroll
            for (int c = 0; c < 4; c++) {
                float v = s[r][c] * scale;
                if (diag && (k0 + tx * 4 + c) > ig) v = -1e30f;
                s[r][c] = v;
            }
        }

        // online softmax: rows are shared by the 16 tx-lanes (xor bits 0..3)
        #pragma unroll
        for (int r = 0; r < 4; r++) {
            float pm = fmaxf(fmaxf(s[r][0], s[r][1]), fmaxf(s[r][2], s[r][3]));
            #pragma unroll
            for (int off = 8; off >= 1; off >>= 1)
                pm = fmaxf(pm, __shfl_xor_sync(0xffffffffu, pm, off));
            float mnew = fmaxf(m[r], pm);
            float corr = __expf(m[r] - mnew);
            m[r] = mnew;
            float rs = 0.f;
            #pragma unroll
            for (int c = 0; c < 4; c++) {
                float p = __expf(s[r][c] - mnew);
                s[r][c] = p;
                rs += p;
            }
            #pragma unroll
            for (int off = 8; off >= 1; off >>= 1)
                rs += __shfl_xor_sync(0xffffffffu, rs, off);
            l[r] = l[r] * corr + rs;
            #pragma unroll
            for (int c = 0; c < 4; c++) o[r][c] *= corr;
        }

        __syncthreads();  // everyone done reading KP as K^T
        // Write P^T into KP: KP[j][i] = P[i][j]
        #pragma unroll
        for (int c = 0; c < 4; c++)
            *(float4*)&KP[tx * 4 + c][ty * 4] =
                make_float4(s[0][c], s[1][c], s[2][c], s[3][c]);
        __syncthreads();

        // O += P @ V   (o[r][c] : query row, d col)
        #pragma unroll 8
        for (int j = 0; j < 64; j++) {
            float4 a4 = *(const float4*)&KP[j][ty * 4];
            float4 v4 = *(const float4*)&Vs[j][tx * 4];
            float a[4]  = {a4.x, a4.y, a4.z, a4.w};
            float vv[4] = {v4.x, v4.y, v4.z, v4.w};
            #pragma unroll
            for (int r = 0; r < 4; r++)
                #pragma unroll
                for (int c = 0; c < 4; c++)
                    o[r][c] += a[r] * vv[c];
        }
    }

    // epilogue: out[b][s][d] = O / l
    float* ob = out + (size_t)b * SS * DD;
    #pragma unroll
    for (int r = 0; r < 4; r++) {
        float inv = 1.0f / l[r];
        float4 o4 = make_float4(o[r][0] * inv, o[r][1] * inv,
                                o[r][2] * inv, o[r][3] * inv);
        *(float4*)&ob[(size_t)(q0 + ty * 4 + r) * DD + tx * 4] = o4;
    }
}

// ---------------------------------------------------------------------------
// Inputs (metadata order): x, mask, Wq, bq, Wk, bk, Wv, bv
// mask is the causal tril mask -> not read (causality hard-coded, exact).
// ---------------------------------------------------------------------------
extern "C" void kernel_launch(void* const* d_in, const int* in_sizes, int n_in,
                              void* d_out, int out_size)
{
    const float* x  = (const float*)d_in[0];
    const float* Wq = (const float*)d_in[2];
    const float* bq = (const float*)d_in[3];
    const float* Wk = (const float*)d_in[4];
    const float* bk = (const float*)d_in[5];
    const float* Wv = (const float*)d_in[6];
    const float* bv = (const float*)d_in[7];
    float* out = (float*)d_out;

    proj_kernel<<<dim3(MTOT / 64, 3), 256>>>(x, Wq, bq, Wk, bk, Wv, bv);
    flash_kernel<<<dim3(SS / 64, BB), 256>>>(out);
}

// round 3
// speedup vs baseline: 2.8456x; 2.8295x over previous
#include <cuda_runtime.h>
#include <cstdint>

#define BBQ 4
#define SSQ 2048
#define EEQ 1024
#define DDQ 64

// tf32-rounded intermediates. Q pre-scaled by 1/sqrt(D), row-major [b*S+s][D].
// K, V transposed [b][d][s] so flash tiles load as contiguous float4 rows.
__device__ float g_q [BBQ * SSQ * DDQ];
__device__ float g_kt[BBQ * DDQ * SSQ];
__device__ float g_vt[BBQ * DDQ * SSQ];

__device__ __forceinline__ uint32_t f2tf(float f) {
    uint32_t u; asm("cvt.rna.tf32.f32 %0, %1;" : "=r"(u) : "f"(f)); return u;
}
__device__ __forceinline__ void mma_tf32(float c[4], const uint32_t a[4],
                                         uint32_t b0, uint32_t b1) {
    asm volatile(
        "mma.sync.aligned.m16n8k8.row.col.f32.tf32.tf32.f32 "
        "{%0,%1,%2,%3},{%4,%5,%6,%7},{%8,%9},{%0,%1,%2,%3};"
        : "+f"(c[0]), "+f"(c[1]), "+f"(c[2]), "+f"(c[3])
        : "r"(a[0]), "r"(a[1]), "r"(a[2]), "r"(a[3]), "r"(b0), "r"(b1));
}

// ---------------------------------------------------------------------------
// Fused QKV projection (tf32 mma). 128 CTAs x 256 thr. 64(M) x 192(N) x 32(K).
// cols 0..63: x@Wk+bk -> g_q (scaled, tf32)   [reference swaps K/Q roles]
// cols 64..127: x@Wq+bq -> g_kt (transposed)
// cols 128..191: x@Wv+bv -> g_vt (transposed)
// ---------------------------------------------------------------------------
__global__ __launch_bounds__(256) void proj_mma(
    const float* __restrict__ x,
    const float* __restrict__ Wq, const float* __restrict__ bq,
    const float* __restrict__ Wk, const float* __restrict__ bk,
    const float* __restrict__ Wv, const float* __restrict__ bv)
{
    __shared__ uint32_t Xs[64 * 36];    // stride 36: banks 4r+q, conflict-free
    __shared__ uint32_t Ws[32 * 200];   // stride 200: banks 8q+r, conflict-free

    const int tid = threadIdx.x, lane = tid & 31, wid = tid >> 5;
    const int wg = wid & 3, half = wid >> 2;
    const int m0 = blockIdx.x * 64;
    const int r = lane >> 2, q = lane & 3;

    float acc[12][4];
    #pragma unroll
    for (int i = 0; i < 12; i++)
        #pragma unroll
        for (int j = 0; j < 4; j++) acc[i][j] = 0.f;

    for (int k0 = 0; k0 < EEQ; k0 += 32) {
        #pragma unroll
        for (int i = 0; i < 2; i++) {
            int idx = tid + i * 256;
            int rr = idx >> 3, c4 = (idx & 7) * 4;
            float4 v = *(const float4*)&x[(size_t)(m0 + rr) * EEQ + k0 + c4];
            *(uint4*)&Xs[rr * 36 + c4] =
                make_uint4(f2tf(v.x), f2tf(v.y), f2tf(v.z), f2tf(v.w));
        }
        #pragma unroll
        for (int i = 0; i < 6; i++) {
            int idx = tid + i * 256;
            int rr = idx / 48, c4 = (idx % 48) * 4;
            const float* Wp = (c4 < 64) ? Wk : (c4 < 128 ? Wq : Wv);
            float4 v = *(const float4*)&Wp[(size_t)(k0 + rr) * DDQ + (c4 & 63)];
            *(uint4*)&Ws[rr * 200 + c4] =
                make_uint4(f2tf(v.x), f2tf(v.y), f2tf(v.z), f2tf(v.w));
        }
        __syncthreads();

        #pragma unroll
        for (int ks = 0; ks < 4; ks++) {
            uint32_t a[4];
            int ra = 16 * wg + r, ca = 8 * ks + q;
            a[0] = Xs[ra * 36 + ca];
            a[1] = Xs[(ra + 8) * 36 + ca];
            a[2] = Xs[ra * 36 + ca + 4];
            a[3] = Xs[(ra + 8) * 36 + ca + 4];
            #pragma unroll
            for (int nt = 0; nt < 12; nt++) {
                int nb = (12 * half + nt) * 8;
                uint32_t b0 = Ws[(8 * ks + q) * 200 + nb + r];
                uint32_t b1 = Ws[(8 * ks + 4 + q) * 200 + nb + r];
                mma_tf32(acc[nt], a, b0, b1);
            }
        }
        __syncthreads();
    }

    #pragma unroll
    for (int nt = 0; nt < 12; nt++) {
        int ng = (12 * half + nt) * 8 + 2 * q;    // even global col
        int blk = ng >> 6, nn = ng & 63;
        const float* bias = (blk == 0) ? bk : (blk == 1 ? bq : bv);
        float b0v = bias[nn], b1v = bias[nn + 1];
        int m = m0 + 16 * wg + r;
        float v00 = acc[nt][0] + b0v, v01 = acc[nt][1] + b1v;   // row m
        float v10 = acc[nt][2] + b0v, v11 = acc[nt][3] + b1v;   // row m+8
        if (blk == 0) { v00 *= 0.125f; v01 *= 0.125f; v10 *= 0.125f; v11 *= 0.125f; }
        v00 = __uint_as_float(f2tf(v00)); v01 = __uint_as_float(f2tf(v01));
        v10 = __uint_as_float(f2tf(v10)); v11 = __uint_as_float(f2tf(v11));
        if (blk == 0) {
            *(float2*)&g_q[(size_t)m * DDQ + nn]       = make_float2(v00, v01);
            *(float2*)&g_q[(size_t)(m + 8) * DDQ + nn] = make_float2(v10, v11);
        } else {
            float* dst = (blk == 1) ? g_kt : g_vt;
            int bb = m >> 11, s = m & (SSQ - 1);
            size_t base = ((size_t)bb * DDQ + nn) * SSQ + s;
            dst[base]           = v00;
            dst[base + SSQ]     = v01;
            dst[base + 8]       = v10;
            dst[base + SSQ + 8] = v11;
        }
    }
}

// ---------------------------------------------------------------------------
// Flash attention (tf32 mma). Grid (32, 4), 256 thr. wg=wid&3 owns query rows
// 16wg..+15; g=wid>>2 picks KV group (even/odd tiles). Groups merged at end.
// ---------------------------------------------------------------------------
#define KSTR 72
#define VSTR 68
#define PSTR 68
#define SMF_VT (2 * 64 * KSTR)               // 9216
#define SMF_PS (SMF_VT + 2 * 64 * VSTR)      // 17920
#define SMF_ML (SMF_PS + 2 * 64 * PSTR)      // 26624
#define SMF_TOT (SMF_ML + 256)               // 26880 floats = 107520 B

__global__ __launch_bounds__(256) void flash_mma(float* __restrict__ out)
{
    extern __shared__ float sm[];
    float* Kt  = sm;                 // also O-staging in merge epilogue
    float* Vt  = sm + SMF_VT;
    float* Ps  = sm + SMF_PS;
    float* mlb = sm + SMF_ML;

    const int tid = threadIdx.x, lane = tid & 31, wid = tid >> 5;
    const int wg = wid & 3, g = wid >> 2;
    const int r = lane >> 2, q = lane & 3;
    const int qt = blockIdx.x, b = blockIdx.y;
    const int q0 = qt * 64, T = qt + 1, NS = (T + 1) >> 1;
    const int rA = 16 * wg + r;

    const float* gq  = g_q  + (size_t)(b * SSQ + q0 + 16 * wg) * DDQ;
    const float* gkt = g_kt + (size_t)b * DDQ * SSQ;
    const float* gvt = g_vt + (size_t)b * DDQ * SSQ;

    uint32_t qa[8][4];
    #pragma unroll
    for (int ks = 0; ks < 8; ks++) {
        int c0 = 8 * ks + q;
        qa[ks][0] = __float_as_uint(gq[(size_t)r * DDQ + c0]);
        qa[ks][1] = __float_as_uint(gq[(size_t)(r + 8) * DDQ + c0]);
        qa[ks][2] = __float_as_uint(gq[(size_t)r * DDQ + c0 + 4]);
        qa[ks][3] = __float_as_uint(gq[(size_t)(r + 8) * DDQ + c0 + 4]);
    }

    float o[8][4];
    #pragma unroll
    for (int i = 0; i < 8; i++)
        #pragma unroll
        for (int j = 0; j < 4; j++) o[i][j] = 0.f;
    float m0r = -1e30f, m1r = -1e30f, l0r = 0.f, l1r = 0.f;

    for (int si = 0; si < NS; si++) {
        if (si > 0) __syncthreads();
        #pragma unroll
        for (int tt = 0; tt < 2; tt++) {
            int tile = 2 * si + tt;
            if (tile < T) {
                int k0c = tile * 64;
                float* KD = Kt + tt * 64 * KSTR;
                float* VD = Vt + tt * 64 * VSTR;
                #pragma unroll
                for (int i = 0; i < 4; i++) {
                    int idx = tid + i * 256;
                    int d = idx >> 4, c4 = (idx & 15) * 4;
                    *(float4*)&KD[d * KSTR + c4] =
                        *(const float4*)&gkt[(size_t)d * SSQ + k0c + c4];
                    *(float4*)&VD[d * VSTR + c4] =
                        *(const float4*)&gvt[(size_t)d * SSQ + k0c + c4];
                }
            }
        }
        __syncthreads();

        int tile = 2 * si + g;
        if (tile < T) {
            const float* KD = Kt + g * 64 * KSTR;
            const float* VD = Vt + g * 64 * VSTR;
            float* PD = Ps + g * 64 * PSTR;

            float s[8][4];
            #pragma unroll
            for (int i = 0; i < 8; i++)
                #pragma unroll
                for (int j = 0; j < 4; j++) s[i][j] = 0.f;
            #pragma unroll
            for (int ks = 0; ks < 8; ks++)
                #pragma unroll
                for (int nt = 0; nt < 8; nt++) {
                    uint32_t b0 = __float_as_uint(KD[(8 * ks + q) * KSTR + 8 * nt + r]);
                    uint32_t b1 = __float_as_uint(KD[(8 * ks + 4 + q) * KSTR + 8 * nt + r]);
                    mma_tf32(s[nt], qa[ks], b0, b1);
                }

            if (tile == qt) {   // diagonal tile: causal mask (local offsets)
                int rB = rA + 8;
                #pragma unroll
                for (int nt = 0; nt < 8; nt++) {
                    int c0 = 8 * nt + 2 * q;
                    if (c0     > rA) s[nt][0] = -1e30f;
                    if (c0 + 1 > rA) s[nt][1] = -1e30f;
                    if (c0     > rB) s[nt][2] = -1e30f;
                    if (c0 + 1 > rB) s[nt][3] = -1e30f;
                }
            }

            float pm0 = -1e30f, pm1 = -1e30f;
            #pragma unroll
            for (int nt = 0; nt < 8; nt++) {
                pm0 = fmaxf(pm0, fmaxf(s[nt][0], s[nt][1]));
                pm1 = fmaxf(pm1, fmaxf(s[nt][2], s[nt][3]));
            }
            pm0 = fmaxf(pm0, __shfl_xor_sync(~0u, pm0, 1));
            pm0 = fmaxf(pm0, __shfl_xor_sync(~0u, pm0, 2));
            pm1 = fmaxf(pm1, __shfl_xor_sync(~0u, pm1, 1));
            pm1 = fmaxf(pm1, __shfl_xor_sync(~0u, pm1, 2));
            float mn0 = fmaxf(m0r, pm0), mn1 = fmaxf(m1r, pm1);
            float c0f = __expf(m0r - mn0), c1f = __expf(m1r - mn1);
            m0r = mn0; m1r = mn1;
            float su0 = 0.f, su1 = 0.f;
            #pragma unroll
            for (int nt = 0; nt < 8; nt++) {
                s[nt][0] = __expf(s[nt][0] - m0r);
                s[nt][1] = __expf(s[nt][1] - m0r);
                s[nt][2] = __expf(s[nt][2] - m1r);
                s[nt][3] = __expf(s[nt][3] - m1r);
                su0 += s[nt][0] + s[nt][1];
                su1 += s[nt][2] + s[nt][3];
            }
            su0 += __shfl_xor_sync(~0u, su0, 1);
            su0 += __shfl_xor_sync(~0u, su0, 2);
            su1 += __shfl_xor_sync(~0u, su1, 1);
            su1 += __shfl_xor_sync(~0u, su1, 2);
            l0r = l0r * c0f + su0;  l1r = l1r * c1f + su1;
            #pragma unroll
            for (int nt = 0; nt < 8; nt++) {
                o[nt][0] *= c0f; o[nt][1] *= c0f;
                o[nt][2] *= c1f; o[nt][3] *= c1f;
            }

            #pragma unroll
            for (int nt = 0; nt < 8; nt++) {
                int cc = 8 * nt + 2 * q;
                *(float2*)&PD[rA * PSTR + cc] = make_float2(
                    __uint_as_float(f2tf(s[nt][0])), __uint_as_float(f2tf(s[nt][1])));
                *(float2*)&PD[(rA + 8) * PSTR + cc] = make_float2(
                    __uint_as_float(f2tf(s[nt][2])), __uint_as_float(f2tf(s[nt][3])));
            }
            __syncwarp();

            #pragma unroll
            for (int ks = 0; ks < 8; ks++) {
                uint32_t pa[4];
                int cc = 8 * ks + q;
                pa[0] = __float_as_uint(PD[rA * PSTR + cc]);
                pa[1] = __float_as_uint(PD[(rA + 8) * PSTR + cc]);
                pa[2] = __float_as_uint(PD[rA * PSTR + cc + 4]);
                pa[3] = __float_as_uint(PD[(rA + 8) * PSTR + cc + 4]);
                #pragma unroll
                for (int nt = 0; nt < 8; nt++) {
                    uint32_t b0 = __float_as_uint(VD[(8 * nt + r) * VSTR + cc]);
                    uint32_t b1 = __float_as_uint(VD[(8 * nt + r) * VSTR + cc + 4]);
                    mma_tf32(o[nt], pa, b0, b1);
                }
            }
        }
    }

    // ---- merge the two KV groups ----
    __syncthreads();
    if (q == 0) {
        mlb[g * 64 + rA]           = m0r;
        mlb[g * 64 + rA + 8]       = m1r;
        mlb[128 + g * 64 + rA]     = l0r;
        mlb[128 + g * 64 + rA + 8] = l1r;
    }
    __syncthreads();
    int og = 1 - g;
    float mo0 = mlb[og * 64 + rA],       mo1 = mlb[og * 64 + rA + 8];
    float lo0 = mlb[128 + og * 64 + rA], lo1 = mlb[128 + og * 64 + rA + 8];
    float M0 = fmaxf(m0r, mo0), M1 = fmaxf(m1r, mo1);
    float sc0 = __expf(m0r - M0), sc1 = __expf(m1r - M1);
    float L0 = l0r * sc0 + lo0 * __expf(mo0 - M0);
    float L1 = l1r * sc1 + lo1 * __expf(mo1 - M1);

    if (g == 1) {
        #pragma unroll
        for (int nt = 0; nt < 8; nt++) {
            int cc = 8 * nt + 2 * q;
            *(float2*)&Kt[rA * KSTR + cc] =
                make_float2(o[nt][0] * sc0, o[nt][1] * sc0);
            *(float2*)&Kt[(rA + 8) * KSTR + cc] =
                make_float2(o[nt][2] * sc1, o[nt][3] * sc1);
        }
    }
    __syncthreads();
    if (g == 0) {
        float* ob = out + (size_t)(b * SSQ + q0) * DDQ;
        float i0 = 1.f / L0, i1 = 1.f / L1;
        #pragma unroll
        for (int nt = 0; nt < 8; nt++) {
            int cc = 8 * nt + 2 * q;
            float2 s0 = *(float2*)&Kt[rA * KSTR + cc];
            float2 s1 = *(float2*)&Kt[(rA + 8) * KSTR + cc];
            *(float2*)&ob[(size_t)rA * DDQ + cc] = make_float2(
                (o[nt][0] * sc0 + s0.x) * i0, (o[nt][1] * sc0 + s0.y) * i0);
            *(float2*)&ob[(size_t)(rA + 8) * DDQ + cc] = make_float2(
                (o[nt][2] * sc1 + s1.x) * i1, (o[nt][3] * sc1 + s1.y) * i1);
        }
    }
}

extern "C" void kernel_launch(void* const* d_in, const int* in_sizes, int n_in,
                              void* d_out, int out_size)
{
    const float* x  = (const float*)d_in[0];
    const float* Wq = (const float*)d_in[2];
    const float* bq = (const float*)d_in[3];
    const float* Wk = (const float*)d_in[4];
    const float* bk = (const float*)d_in[5];
    const float* Wv = (const float*)d_in[6];
    const float* bv = (const float*)d_in[7];
    float* out = (float*)d_out;

    cudaFuncSetAttribute(flash_mma, cudaFuncAttributeMaxDynamicSharedMemorySize,
                         SMF_TOT * 4);
    proj_mma<<<BBQ * SSQ / 64, 256>>>(x, Wq, bq, Wk, bk, Wv, bv);
    flash_mma<<<dim3(SSQ / 64, BBQ), 256, SMF_TOT * 4>>>(out);
}

// round 4
// speedup vs baseline: 2.8992x; 1.0188x over previous
#include <cuda_runtime.h>
#include <cstdint>

#define BBQ 4
#define SSQ 2048
#define EEQ 1024
#define DDQ 64

// tf32-rounded intermediates. Q pre-scaled by 1/sqrt(D), row-major [b*S+s][D].
// K, V transposed [b][d][s] so flash tiles load as contiguous float4 rows.
__device__ float g_q [BBQ * SSQ * DDQ];
__device__ float g_kt[BBQ * DDQ * SSQ];
__device__ float g_vt[BBQ * DDQ * SSQ];

__device__ __forceinline__ uint32_t f2tf(float f) {
    uint32_t u; asm("cvt.rna.tf32.f32 %0, %1;" : "=r"(u) : "f"(f)); return u;
}
__device__ __forceinline__ void mma_tf32(float c[4], const uint32_t a[4],
                                         uint32_t b0, uint32_t b1) {
    asm volatile(
        "mma.sync.aligned.m16n8k8.row.col.f32.tf32.tf32.f32 "
        "{%0,%1,%2,%3},{%4,%5,%6,%7},{%8,%9},{%0,%1,%2,%3};"
        : "+f"(c[0]), "+f"(c[1]), "+f"(c[2]), "+f"(c[3])
        : "r"(a[0]), "r"(a[1]), "r"(a[2]), "r"(a[3]), "r"(b0), "r"(b1));
}

// ---------------------------------------------------------------------------
// Fused QKV projection (tf32 mma). 128 CTAs x 256 thr. 64(M) x 192(N) x 32(K).
// cols 0..63: x@Wk+bk -> g_q (scaled, tf32)   [reference swaps K/Q roles]
// cols 64..127: x@Wq+bq -> g_kt (transposed)
// cols 128..191: x@Wv+bv -> g_vt (transposed)
// ---------------------------------------------------------------------------
__global__ __launch_bounds__(256) void proj_mma(
    const float* __restrict__ x,
    const float* __restrict__ Wq, const float* __restrict__ bq,
    const float* __restrict__ Wk, const float* __restrict__ bk,
    const float* __restrict__ Wv, const float* __restrict__ bv)
{
    __shared__ uint32_t Xs[64 * 36];    // stride 36: banks 4r+q, conflict-free
    __shared__ uint32_t Ws[32 * 200];   // stride 200: banks 8q+r, conflict-free

    const int tid = threadIdx.x, lane = tid & 31, wid = tid >> 5;
    const int wg = wid & 3, half = wid >> 2;
    const int m0 = blockIdx.x * 64;
    const int r = lane >> 2, q = lane & 3;

    float acc[12][4];
    #pragma unroll
    for (int i = 0; i < 12; i++)
        #pragma unroll
        for (int j = 0; j < 4; j++) acc[i][j] = 0.f;

    for (int k0 = 0; k0 < EEQ; k0 += 32) {
        #pragma unroll
        for (int i = 0; i < 2; i++) {
            int idx = tid + i * 256;
            int rr = idx >> 3, c4 = (idx & 7) * 4;
            float4 v = *(const float4*)&x[(size_t)(m0 + rr) * EEQ + k0 + c4];
            *(uint4*)&Xs[rr * 36 + c4] =
                make_uint4(f2tf(v.x), f2tf(v.y), f2tf(v.z), f2tf(v.w));
        }
        #pragma unroll
        for (int i = 0; i < 6; i++) {
            int idx = tid + i * 256;
            int rr = idx / 48, c4 = (idx % 48) * 4;
            const float* Wp = (c4 < 64) ? Wk : (c4 < 128 ? Wq : Wv);
            float4 v = *(const float4*)&Wp[(size_t)(k0 + rr) * DDQ + (c4 & 63)];
            *(uint4*)&Ws[rr * 200 + c4] =
                make_uint4(f2tf(v.x), f2tf(v.y), f2tf(v.z), f2tf(v.w));
        }
        __syncthreads();

        #pragma unroll
        for (int ks = 0; ks < 4; ks++) {
            uint32_t a[4];
            int ra = 16 * wg + r, ca = 8 * ks + q;
            a[0] = Xs[ra * 36 + ca];
            a[1] = Xs[(ra + 8) * 36 + ca];
            a[2] = Xs[ra * 36 + ca + 4];
            a[3] = Xs[(ra + 8) * 36 + ca + 4];
            #pragma unroll
            for (int nt = 0; nt < 12; nt++) {
                int nb = (12 * half + nt) * 8;
                uint32_t b0 = Ws[(8 * ks + q) * 200 + nb + r];
                uint32_t b1 = Ws[(8 * ks + 4 + q) * 200 + nb + r];
                mma_tf32(acc[nt], a, b0, b1);
            }
        }
        __syncthreads();
    }

    #pragma unroll
    for (int nt = 0; nt < 12; nt++) {
        int ng = (12 * half + nt) * 8 + 2 * q;    // even global col
        int blk = ng >> 6, nn = ng & 63;
        const float* bias = (blk == 0) ? bk : (blk == 1 ? bq : bv);
        float b0v = bias[nn], b1v = bias[nn + 1];
        int m = m0 + 16 * wg + r;
        float v00 = acc[nt][0] + b0v, v01 = acc[nt][1] + b1v;   // row m
        float v10 = acc[nt][2] + b0v, v11 = acc[nt][3] + b1v;   // row m+8
        if (blk == 0) { v00 *= 0.125f; v01 *= 0.125f; v10 *= 0.125f; v11 *= 0.125f; }
        v00 = __uint_as_float(f2tf(v00)); v01 = __uint_as_float(f2tf(v01));
        v10 = __uint_as_float(f2tf(v10)); v11 = __uint_as_float(f2tf(v11));
        if (blk == 0) {
            *(float2*)&g_q[(size_t)m * DDQ + nn]       = make_float2(v00, v01);
            *(float2*)&g_q[(size_t)(m + 8) * DDQ + nn] = make_float2(v10, v11);
        } else {
            float* dst = (blk == 1) ? g_kt : g_vt;
            int bb = m >> 11, s = m & (SSQ - 1);
            size_t base = ((size_t)bb * DDQ + nn) * SSQ + s;
            dst[base]           = v00;
            dst[base + SSQ]     = v01;
            dst[base + 8]       = v10;
            dst[base + SSQ + 8] = v11;
        }
    }
}

// ---------------------------------------------------------------------------
// Flash attention (tf32 mma). Grid (32, 4), 256 thr. wg=wid&3 owns query rows
// 16wg..+15; g=wid>>2 picks KV group (even/odd tiles). Groups merged at end.
// ---------------------------------------------------------------------------
#define KSTR 72
#define VSTR 68
#define PSTR 68
#define SMF_VT (2 * 64 * KSTR)               // 9216
#define SMF_PS (SMF_VT + 2 * 64 * VSTR)      // 17920
#define SMF_ML (SMF_PS + 2 * 64 * PSTR)      // 26624
#define SMF_TOT (SMF_ML + 256)               // 26880 floats = 107520 B

__global__ __launch_bounds__(256) void flash_mma(float* __restrict__ out)
{
    extern __shared__ float sm[];
    float* Kt  = sm;                 // also O-staging in merge epilogue
    float* Vt  = sm + SMF_VT;
    float* Ps  = sm + SMF_PS;
    float* mlb = sm + SMF_ML;

    const int tid = threadIdx.x, lane = tid & 31, wid = tid >> 5;
    const int wg = wid & 3, g = wid >> 2;
    const int r = lane >> 2, q = lane & 3;
    const int qt = blockIdx.x, b = blockIdx.y;
    const int q0 = qt * 64, T = qt + 1, NS = (T + 1) >> 1;
    const int rA = 16 * wg + r;

    const float* gq  = g_q  + (size_t)(b * SSQ + q0 + 16 * wg) * DDQ;
    const float* gkt = g_kt + (size_t)b * DDQ * SSQ;
    const float* gvt = g_vt + (size_t)b * DDQ * SSQ;

    uint32_t qa[8][4];
    #pragma unroll
    for (int ks = 0; ks < 8; ks++) {
        int c0 = 8 * ks + q;
        qa[ks][0] = __float_as_uint(gq[(size_t)r * DDQ + c0]);
        qa[ks][1] = __float_as_uint(gq[(size_t)(r + 8) * DDQ + c0]);
        qa[ks][2] = __float_as_uint(gq[(size_t)r * DDQ + c0 + 4]);
        qa[ks][3] = __float_as_uint(gq[(size_t)(r + 8) * DDQ + c0 + 4]);
    }

    float o[8][4];
    #pragma unroll
    for (int i = 0; i < 8; i++)
        #pragma unroll
        for (int j = 0; j < 4; j++) o[i][j] = 0.f;
    float m0r = -1e30f, m1r = -1e30f, l0r = 0.f, l1r = 0.f;

    for (int si = 0; si < NS; si++) {
        if (si > 0) __syncthreads();
        #pragma unroll
        for (int tt = 0; tt < 2; tt++) {
            int tile = 2 * si + tt;
            if (tile < T) {
                int k0c = tile * 64;
                float* KD = Kt + tt * 64 * KSTR;
                float* VD = Vt + tt * 64 * VSTR;
                #pragma unroll
                for (int i = 0; i < 4; i++) {
                    int idx = tid + i * 256;
                    int d = idx >> 4, c4 = (idx & 15) * 4;
                    *(float4*)&KD[d * KSTR + c4] =
                        *(const float4*)&gkt[(size_t)d * SSQ + k0c + c4];
                    *(float4*)&VD[d * VSTR + c4] =
                        *(const float4*)&gvt[(size_t)d * SSQ + k0c + c4];
                }
            }
        }
        __syncthreads();

        int tile = 2 * si + g;
        if (tile < T) {
            const float* KD = Kt + g * 64 * KSTR;
            const float* VD = Vt + g * 64 * VSTR;
            float* PD = Ps + g * 64 * PSTR;

            float s[8][4];
            #pragma unroll
            for (int i = 0; i < 8; i++)
                #pragma unroll
                for (int j = 0; j < 4; j++) s[i][j] = 0.f;
            #pragma unroll
            for (int ks = 0; ks < 8; ks++)
                #pragma unroll
                for (int nt = 0; nt < 8; nt++) {
                    uint32_t b0 = __float_as_uint(KD[(8 * ks + q) * KSTR + 8 * nt + r]);
                    uint32_t b1 = __float_as_uint(KD[(8 * ks + 4 + q) * KSTR + 8 * nt + r]);
                    mma_tf32(s[nt], qa[ks], b0, b1);
                }

            if (tile == qt) {   // diagonal tile: causal mask (local offsets)
                int rB = rA + 8;
                #pragma unroll
                for (int nt = 0; nt < 8; nt++) {
                    int c0 = 8 * nt + 2 * q;
                    if (c0     > rA) s[nt][0] = -1e30f;
                    if (c0 + 1 > rA) s[nt][1] = -1e30f;
                    if (c0     > rB) s[nt][2] = -1e30f;
                    if (c0 + 1 > rB) s[nt][3] = -1e30f;
                }
            }

            float pm0 = -1e30f, pm1 = -1e30f;
            #pragma unroll
            for (int nt = 0; nt < 8; nt++) {
                pm0 = fmaxf(pm0, fmaxf(s[nt][0], s[nt][1]));
                pm1 = fmaxf(pm1, fmaxf(s[nt][2], s[nt][3]));
            }
            pm0 = fmaxf(pm0, __shfl_xor_sync(~0u, pm0, 1));
            pm0 = fmaxf(pm0, __shfl_xor_sync(~0u, pm0, 2));
            pm1 = fmaxf(pm1, __shfl_xor_sync(~0u, pm1, 1));
            pm1 = fmaxf(pm1, __shfl_xor_sync(~0u, pm1, 2));
            float mn0 = fmaxf(m0r, pm0), mn1 = fmaxf(m1r, pm1);
            float c0f = __expf(m0r - mn0), c1f = __expf(m1r - mn1);
            m0r = mn0; m1r = mn1;
            float su0 = 0.f, su1 = 0.f;
            #pragma unroll
            for (int nt = 0; nt < 8; nt++) {
                s[nt][0] = __expf(s[nt][0] - m0r);
                s[nt][1] = __expf(s[nt][1] - m0r);
                s[nt][2] = __expf(s[nt][2] - m1r);
                s[nt][3] = __expf(s[nt][3] - m1r);
                su0 += s[nt][0] + s[nt][1];
                su1 += s[nt][2] + s[nt][3];
            }
            su0 += __shfl_xor_sync(~0u, su0, 1);
            su0 += __shfl_xor_sync(~0u, su0, 2);
            su1 += __shfl_xor_sync(~0u, su1, 1);
            su1 += __shfl_xor_sync(~0u, su1, 2);
            l0r = l0r * c0f + su0;  l1r = l1r * c1f + su1;
            #pragma unroll
            for (int nt = 0; nt < 8; nt++) {
                o[nt][0] *= c0f; o[nt][1] *= c0f;
                o[nt][2] *= c1f; o[nt][3] *= c1f;
            }

            #pragma unroll
            for (int nt = 0; nt < 8; nt++) {
                int cc = 8 * nt + 2 * q;
                *(float2*)&PD[rA * PSTR + cc] = make_float2(
                    __uint_as_float(f2tf(s[nt][0])), __uint_as_float(f2tf(s[nt][1])));
                *(float2*)&PD[(rA + 8) * PSTR + cc] = make_float2(
                    __uint_as_float(f2tf(s[nt][2])), __uint_as_float(f2tf(s[nt][3])));
            }
            __syncwarp();

            #pragma unroll
            for (int ks = 0; ks < 8; ks++) {
                uint32_t pa[4];
                int cc = 8 * ks + q;
                pa[0] = __float_as_uint(PD[rA * PSTR + cc]);
                pa[1] = __float_as_uint(PD[(rA + 8) * PSTR + cc]);
                pa[2] = __float_as_uint(PD[rA * PSTR + cc + 4]);
                pa[3] = __float_as_uint(PD[(rA + 8) * PSTR + cc + 4]);
                #pragma unroll
                for (int nt = 0; nt < 8; nt++) {
                    uint32_t b0 = __float_as_uint(VD[(8 * nt + r) * VSTR + cc]);
                    uint32_t b1 = __float_as_uint(VD[(8 * nt + r) * VSTR + cc + 4]);
                    mma_tf32(o[nt], pa, b0, b1);
                }
            }
        }
    }

    // ---- merge the two KV groups ----
    __syncthreads();
    if (q == 0) {
        mlb[g * 64 + rA]           = m0r;
        mlb[g * 64 + rA + 8]       = m1r;
        mlb[128 + g * 64 + rA]     = l0r;
        mlb[128 + g * 64 + rA + 8] = l1r;
    }
    __syncthreads();
    int og = 1 - g;
    float mo0 = mlb[og * 64 + rA],       mo1 = mlb[og * 64 + rA + 8];
    float lo0 = mlb[128 + og * 64 + rA], lo1 = mlb[128 + og * 64 + rA + 8];
    float M0 = fmaxf(m0r, mo0), M1 = fmaxf(m1r, mo1);
    float sc0 = __expf(m0r - M0), sc1 = __expf(m1r - M1);
    float L0 = l0r * sc0 + lo0 * __expf(mo0 - M0);
    float L1 = l1r * sc1 + lo1 * __expf(mo1 - M1);

    if (g == 1) {
        #pragma unroll
        for (int nt = 0; nt < 8; nt++) {
            int cc = 8 * nt + 2 * q;
            *(float2*)&Kt[rA * KSTR + cc] =
                make_float2(o[nt][0] * sc0, o[nt][1] * sc0);
            *(float2*)&Kt[(rA + 8) * KSTR + cc] =
                make_float2(o[nt][2] * sc1, o[nt][3] * sc1);
        }
    }
    __syncthreads();
    if (g == 0) {
        float* ob = out + (size_t)(b * SSQ + q0) * DDQ;
        float i0 = 1.f / L0, i1 = 1.f / L1;
        #pragma unroll
        for (int nt = 0; nt < 8; nt++) {
            int cc = 8 * nt + 2 * q;
            float2 s0 = *(float2*)&Kt[rA * KSTR + cc];
            float2 s1 = *(float2*)&Kt[(rA + 8) * KSTR + cc];
            *(float2*)&ob[(size_t)rA * DDQ + cc] = make_float2(
                (o[nt][0] * sc0 + s0.x) * i0, (o[nt][1] * sc0 + s0.y) * i0);
            *(float2*)&ob[(size_t)(rA + 8) * DDQ + cc] = make_float2(
                (o[nt][2] * sc1 + s1.x) * i1, (o[nt][3] * sc1 + s1.y) * i1);
        }
    }
}

extern "C" void kernel_launch(void* const* d_in, const int* in_sizes, int n_in,
                              void* d_out, int out_size)
{
    const float* x  = (const float*)d_in[0];
    const float* Wq = (const float*)d_in[2];
    const float* bq = (const float*)d_in[3];
    const float* Wk = (const float*)d_in[4];
    const float* bk = (const float*)d_in[5];
    const float* Wv = (const float*)d_in[6];
    const float* bv = (const float*)d_in[7];
    float* out = (float*)d_out;

    cudaFuncSetAttribute(flash_mma, cudaFuncAttributeMaxDynamicSharedMemorySize,
                         SMF_TOT * 4);
    proj_mma<<<BBQ * SSQ / 64, 256>>>(x, Wq, bq, Wk, bk, Wv, bv);
    flash_mma<<<dim3(SSQ / 64, BBQ), 256, SMF_TOT * 4>>>(out);
}

// round 5
// speedup vs baseline: 3.7206x; 1.2833x over previous
#include <cuda_runtime.h>
#include <cuda_fp16.h>
#include <cstdint>

#define BB 4
#define SS 2048
#define EE 1024
#define DD 64

__device__ __align__(16) __half g_q [BB * SS * DD];   // scaled 1/8, [m][d]
__device__ __align__(16) __half g_k [BB * SS * DD];   // [m][d]
__device__ __align__(16) __half g_vt[BB * DD * SS];   // [b][d][s]

__device__ __forceinline__ uint32_t f2tf(float f) {
    uint32_t u; asm("cvt.rna.tf32.f32 %0, %1;" : "=r"(u) : "f"(f)); return u;
}
__device__ __forceinline__ uint32_t packh2(float a, float b) {
    __half2 h = __floats2half2_rn(a, b); return *(uint32_t*)&h;
}
__device__ __forceinline__ void mma_tf32(float c[4], const uint32_t a[4],
                                         uint32_t b0, uint32_t b1) {
    asm volatile("mma.sync.aligned.m16n8k8.row.col.f32.tf32.tf32.f32 "
        "{%0,%1,%2,%3},{%4,%5,%6,%7},{%8,%9},{%0,%1,%2,%3};"
        : "+f"(c[0]), "+f"(c[1]), "+f"(c[2]), "+f"(c[3])
        : "r"(a[0]), "r"(a[1]), "r"(a[2]), "r"(a[3]), "r"(b0), "r"(b1));
}
__device__ __forceinline__ void mma_f16(float c[4], const uint32_t a[4],
                                        uint32_t b0, uint32_t b1) {
    asm volatile("mma.sync.aligned.m16n8k16.row.col.f32.f16.f16.f32 "
        "{%0,%1,%2,%3},{%4,%5,%6,%7},{%8,%9},{%0,%1,%2,%3};"
        : "+f"(c[0]), "+f"(c[1]), "+f"(c[2]), "+f"(c[3])
        : "r"(a[0]), "r"(a[1]), "r"(a[2]), "r"(a[3]), "r"(b0), "r"(b1));
}
__device__ __forceinline__ void cp16(uint32_t d, const void* s) {
    asm volatile("cp.async.cg.shared.global [%0], [%1], 16;" :: "r"(d), "l"(s));
}

// ---------------- projection: tf32 core, fp16 epilogue ----------------
__global__ __launch_bounds__(256) void proj_mma(
    const float* __restrict__ x,
    const float* __restrict__ Wq, const float* __restrict__ bq,
    const float* __restrict__ Wk, const float* __restrict__ bk,
    const float* __restrict__ Wv, const float* __restrict__ bv)
{
    __shared__ uint32_t Xs[64 * 36];
    __shared__ uint32_t Ws[32 * 200];
    const int tid = threadIdx.x, lane = tid & 31, wid = tid >> 5;
    const int wg = wid & 3, half = wid >> 2;
    const int m0 = blockIdx.x * 64;
    const int r = lane >> 2, q = lane & 3;

    float acc[12][4];
    #pragma unroll
    for (int i = 0; i < 12; i++)
        #pragma unroll
        for (int j = 0; j < 4; j++) acc[i][j] = 0.f;

    for (int k0 = 0; k0 < EE; k0 += 32) {
        #pragma unroll
        for (int i = 0; i < 2; i++) {
            int idx = tid + i * 256;
            int rr = idx >> 3, c4 = (idx & 7) * 4;
            float4 v = *(const float4*)&x[(size_t)(m0 + rr) * EE + k0 + c4];
            *(uint4*)&Xs[rr * 36 + c4] =
                make_uint4(f2tf(v.x), f2tf(v.y), f2tf(v.z), f2tf(v.w));
        }
        #pragma unroll
        for (int i = 0; i < 6; i++) {
            int idx = tid + i * 256;
            int rr = idx / 48, c4 = (idx % 48) * 4;
            const float* Wp = (c4 < 64) ? Wk : (c4 < 128 ? Wq : Wv);
            float4 v = *(const float4*)&Wp[(size_t)(k0 + rr) * DD + (c4 & 63)];
            *(uint4*)&Ws[rr * 200 + c4] =
                make_uint4(f2tf(v.x), f2tf(v.y), f2tf(v.z), f2tf(v.w));
        }
        __syncthreads();
        #pragma unroll
        for (int ks = 0; ks < 4; ks++) {
            uint32_t a[4];
            int ra = 16 * wg + r, ca = 8 * ks + q;
            a[0] = Xs[ra * 36 + ca];       a[1] = Xs[(ra + 8) * 36 + ca];
            a[2] = Xs[ra * 36 + ca + 4];   a[3] = Xs[(ra + 8) * 36 + ca + 4];
            #pragma unroll
            for (int nt = 0; nt < 12; nt++) {
                int nb = (12 * half + nt) * 8;
                mma_tf32(acc[nt], a, Ws[(8 * ks + q) * 200 + nb + r],
                         Ws[(8 * ks + 4 + q) * 200 + nb + r]);
            }
        }
        __syncthreads();
    }

    #pragma unroll
    for (int nt = 0; nt < 12; nt++) {
        int ng = (12 * half + nt) * 8 + 2 * q;
        int blk = ng >> 6, nn = ng & 63;
        const float* bias = (blk == 0) ? bk : (blk == 1 ? bq : bv);
        float b0v = bias[nn], b1v = bias[nn + 1];
        int m = m0 + 16 * wg + r;
        float v00 = acc[nt][0] + b0v, v01 = acc[nt][1] + b1v;
        float v10 = acc[nt][2] + b0v, v11 = acc[nt][3] + b1v;
        if (blk == 0) {
            *(uint32_t*)&g_q[(size_t)m * DD + nn] = packh2(v00 * .125f, v01 * .125f);
            *(uint32_t*)&g_q[(size_t)(m + 8) * DD + nn] = packh2(v10 * .125f, v11 * .125f);
        } else if (blk == 1) {
            *(uint32_t*)&g_k[(size_t)m * DD + nn]       = packh2(v00, v01);
            *(uint32_t*)&g_k[(size_t)(m + 8) * DD + nn] = packh2(v10, v11);
        } else {
            int bb = m >> 11, s = m & (SS - 1);
            size_t base = ((size_t)bb * DD + nn) * SS + s;
            g_vt[base]          = __float2half(v00);
            g_vt[base + SS]     = __float2half(v01);
            g_vt[base + 8]      = __float2half(v10);
            g_vt[base + SS + 8] = __float2half(v11);
        }
    }
}

// ---------------- flash attention, fp16 mma ----------------
#define KH 72   // half stride (36 u32: conflict-free)
#define OSTR 68
__global__ __launch_bounds__(256) void flash_fa(float* __restrict__ out)
{
    __shared__ __align__(16) char smraw[2 * 64 * KH * 2 * 2 + 1024];
    __half* Kt = (__half*)smraw;
    __half* Vt = Kt + 2 * 64 * KH;
    float* mlb = (float*)(smraw + 2 * (2 * 64 * KH) * 2);
    float* Of  = (float*)smraw;   // epilogue reuse

    const int tid = threadIdx.x, lane = tid & 31, wid = tid >> 5;
    const int wg = wid & 3, g = wid >> 2;
    const int r = lane >> 2, q = lane & 3;
    const int qt = blockIdx.x, b = blockIdx.y;
    const int q0 = qt * 64, T = qt + 1, NS = (T + 1) >> 1;
    const int rA = 16 * wg + r;

    const __half* gq = g_q + (size_t)(b * SS + q0 + 16 * wg) * DD;
    const __half* gk = g_k + (size_t)b * SS * DD;
    const __half* gv = g_vt + (size_t)b * DD * SS;

    uint32_t qa[4][4];
    #pragma unroll
    for (int ks = 0; ks < 4; ks++) {
        int c0 = 16 * ks + 2 * q;
        qa[ks][0] = *(const uint32_t*)&gq[(size_t)r * DD + c0];
        qa[ks][1] = *(const uint32_t*)&gq[(size_t)(r + 8) * DD + c0];
        qa[ks][2] = *(const uint32_t*)&gq[(size_t)r * DD + c0 + 8];
        qa[ks][3] = *(const uint32_t*)&gq[(size_t)(r + 8) * DD + c0 + 8];
    }

    float o[8][4];
    #pragma unroll
    for (int i = 0; i < 8; i++)
        #pragma unroll
        for (int j = 0; j < 4; j++) o[i][j] = 0.f;
    float m0r = -1e30f, m1r = -1e30f, l0r = 0.f, l1r = 0.f;

    for (int si = 0; si < NS; si++) {
        if (si > 0) __syncthreads();
        #pragma unroll
        for (int tt = 0; tt < 2; tt++) {
            int tile = 2 * si + tt;
            if (tile < T) {
                int k0c = tile * 64;
                #pragma unroll
                for (int i = 0; i < 2; i++) {
                    int idx = tid + i * 256;
                    int row = idx >> 3, c8 = (idx & 7) * 8;
                    cp16((uint32_t)__cvta_generic_to_shared(
                             &Kt[(tt * 64 + row) * KH + c8]),
                         gk + (size_t)(k0c + row) * DD + c8);
                    cp16((uint32_t)__cvta_generic_to_shared(
                             &Vt[(tt * 64 + row) * KH + c8]),
                         gv + (size_t)row * SS + k0c + c8);
                }
            }
        }
        asm volatile("cp.async.commit_group;");
        asm volatile("cp.async.wait_group 0;");
        __syncthreads();

        int tile = 2 * si + g;
        if (tile < T) {
            const __half* KD = Kt + g * 64 * KH;
            const __half* VD = Vt + g * 64 * KH;

            float s[8][4];
            #pragma unroll
            for (int i = 0; i < 8; i++)
                #pragma unroll
                for (int j = 0; j < 4; j++) s[i][j] = 0.f;
            #pragma unroll
            for (int ks = 0; ks < 4; ks++)
                #pragma unroll
                for (int nt = 0; nt < 8; nt++) {
                    uint32_t b0 = *(const uint32_t*)&KD[(8 * nt + r) * KH + 16 * ks + 2 * q];
                    uint32_t b1 = *(const uint32_t*)&KD[(8 * nt + r) * KH + 16 * ks + 8 + 2 * q];
                    mma_f16(s[nt], qa[ks], b0, b1);
                }

            if (tile == qt) {
                int rB = rA + 8;
                #pragma unroll
                for (int nt = 0; nt < 8; nt++) {
                    int c0 = 8 * nt + 2 * q;
                    if (c0     > rA) s[nt][0] = -1e30f;
                    if (c0 + 1 > rA) s[nt][1] = -1e30f;
                    if (c0     > rB) s[nt][2] = -1e30f;
                    if (c0 + 1 > rB) s[nt][3] = -1e30f;
                }
            }

            float pm0 = -1e30f, pm1 = -1e30f;
            #pragma unroll
            for (int nt = 0; nt < 8; nt++) {
                pm0 = fmaxf(pm0, fmaxf(s[nt][0], s[nt][1]));
                pm1 = fmaxf(pm1, fmaxf(s[nt][2], s[nt][3]));
            }
            pm0 = fmaxf(pm0, __shfl_xor_sync(~0u, pm0, 1));
            pm0 = fmaxf(pm0, __shfl_xor_sync(~0u, pm0, 2));
            pm1 = fmaxf(pm1, __shfl_xor_sync(~0u, pm1, 1));
            pm1 = fmaxf(pm1, __shfl_xor_sync(~0u, pm1, 2));
            float mn0 = fmaxf(m0r, pm0), mn1 = fmaxf(m1r, pm1);
            float c0f = __expf(m0r - mn0), c1f = __expf(m1r - mn1);
            m0r = mn0; m1r = mn1;
            float su0 = 0.f, su1 = 0.f;
            #pragma unroll
            for (int nt = 0; nt < 8; nt++) {
                s[nt][0] = __expf(s[nt][0] - m0r);
                s[nt][1] = __expf(s[nt][1] - m0r);
                s[nt][2] = __expf(s[nt][2] - m1r);
                s[nt][3] = __expf(s[nt][3] - m1r);
                su0 += s[nt][0] + s[nt][1];
                su1 += s[nt][2] + s[nt][3];
            }
            su0 += __shfl_xor_sync(~0u, su0, 1);
            su0 += __shfl_xor_sync(~0u, su0, 2);
            su1 += __shfl_xor_sync(~0u, su1, 1);
            su1 += __shfl_xor_sync(~0u, su1, 2);
            l0r = l0r * c0f + su0;  l1r = l1r * c1f + su1;
            #pragma unroll
            for (int nt = 0; nt < 8; nt++) {
                o[nt][0] *= c0f; o[nt][1] *= c0f;
                o[nt][2] *= c1f; o[nt][3] *= c1f;
            }

            // P@V: P fragments come straight from s (FA2 layout identity)
            #pragma unroll
            for (int t = 0; t < 4; t++) {
                uint32_t pa[4];
                pa[0] = packh2(s[2 * t][0],     s[2 * t][1]);
                pa[1] = packh2(s[2 * t][2],     s[2 * t][3]);
                pa[2] = packh2(s[2 * t + 1][0], s[2 * t + 1][1]);
                pa[3] = packh2(s[2 * t + 1][2], s[2 * t + 1][3]);
                #pragma unroll
                for (int nt = 0; nt < 8; nt++) {
                    uint32_t b0 = *(const uint32_t*)&VD[(8 * nt + r) * KH + 16 * t + 2 * q];
                    uint32_t b1 = *(const uint32_t*)&VD[(8 * nt + r) * KH + 16 * t + 8 + 2 * q];
                    mma_f16(o[nt], pa, b0, b1);
                }
            }
        }
    }

    // ---- merge two KV groups ----
    __syncthreads();
    if (q == 0) {
        mlb[g * 64 + rA]           = m0r;
        mlb[g * 64 + rA + 8]       = m1r;
        mlb[128 + g * 64 + rA]     = l0r;
        mlb[128 + g * 64 + rA + 8] = l1r;
    }
    __syncthreads();
    int og = 1 - g;
    float mo0 = mlb[og * 64 + rA],       mo1 = mlb[og * 64 + rA + 8];
    float lo0 = mlb[128 + og * 64 + rA], lo1 = mlb[128 + og * 64 + rA + 8];
    float M0 = fmaxf(m0r, mo0), M1 = fmaxf(m1r, mo1);
    float sc0 = __expf(m0r - M0), sc1 = __expf(m1r - M1);
    float L0 = l0r * sc0 + lo0 * __expf(mo0 - M0);
    float L1 = l1r * sc1 + lo1 * __expf(mo1 - M1);
    __syncthreads();   // done reading mlb region? (mlb separate from Of) - ensure Kt reads done
    if (g == 1) {
        #pragma unroll
        for (int nt = 0; nt < 8; nt++) {
            int cc = 8 * nt + 2 * q;
            *(float2*)&Of[rA * OSTR + cc] =
                make_float2(o[nt][0] * sc0, o[nt][1] * sc0);
            *(float2*)&Of[(rA + 8) * OSTR + cc] =
                make_float2(o[nt][2] * sc1, o[nt][3] * sc1);
        }
    }
    __syncthreads();
    if (g == 0) {
        float* ob = out + (size_t)(b * SS + q0) * DD;
        float i0 = 1.f / L0, i1 = 1.f / L1;
        #pragma unroll
        for (int nt = 0; nt < 8; nt++) {
            int cc = 8 * nt + 2 * q;
            float2 s0 = *(float2*)&Of[rA * OSTR + cc];
            float2 s1 = *(float2*)&Of[(rA + 8) * OSTR + cc];
            *(float2*)&ob[(size_t)rA * DD + cc] = make_float2(
                (o[nt][0] * sc0 + s0.x) * i0, (o[nt][1] * sc0 + s0.y) * i0);
            *(float2*)&ob[(size_t)(rA + 8) * DD + cc] = make_float2(
                (o[nt][2] * sc1 + s1.x) * i1, (o[nt][3] * sc1 + s1.y) * i1);
        }
    }
}

extern "C" void kernel_launch(void* const* d_in, const int* in_sizes, int n_in,
                              void* d_out, int out_size)
{
    const float* x  = (const float*)d_in[0];
    const float* Wq = (const float*)d_in[2];
    const float* bq = (const float*)d_in[3];
    const float* Wk = (const float*)d_in[4];
    const float* bk = (const float*)d_in[5];
    const float* Wv = (const float*)d_in[6];
    const float* bv = (const float*)d_in[7];
    float* out = (float*)d_out;

    proj_mma<<<BB * SS / 64, 256>>>(x, Wq, bq, Wk, bk, Wv, bv);
    flash_fa<<<dim3(SS / 64, BB), 256>>>(out);
}

// round 6
// speedup vs baseline: 4.9275x; 1.3244x over previous
#include <cuda_runtime.h>
#include <cuda_fp16.h>
#include <cstdint>

#define BB 4
#define SS 2048
#define EE 1024
#define DD 64

__device__ __align__(16) __half g_q [BB * SS * DD];   // scaled 1/8
__device__ __align__(16) __half g_k [BB * SS * DD];
__device__ __align__(16) __half g_vt[BB * DD * SS];   // [b][d][s]
__device__ __align__(16) __half g_Wt[192 * EE];       // [n][k]: 0-63 Wk,64-127 Wq,128-191 Wv
__device__ float g_part[BB * 32 * 8 * 64 * 64];       // partial O
__device__ float g_ml  [BB * 32 * 8 * 128];           // per-chunk M[64], L[64]

__device__ __forceinline__ uint32_t packh2(float a, float b) {
    __half2 h = __floats2half2_rn(a, b); return *(uint32_t*)&h;
}
__device__ __forceinline__ void mma_f16(float c[4], const uint32_t a[4],
                                        uint32_t b0, uint32_t b1) {
    asm volatile("mma.sync.aligned.m16n8k16.row.col.f32.f16.f16.f32 "
        "{%0,%1,%2,%3},{%4,%5,%6,%7},{%8,%9},{%0,%1,%2,%3};"
        : "+f"(c[0]), "+f"(c[1]), "+f"(c[2]), "+f"(c[3])
        : "r"(a[0]), "r"(a[1]), "r"(a[2]), "r"(a[3]), "r"(b0), "r"(b1));
}
__device__ __forceinline__ void cp16(uint32_t d, const void* s) {
    asm volatile("cp.async.cg.shared.global [%0], [%1], 16;" :: "r"(d), "l"(s));
}

// ---------------- W transpose + fp16 convert (one-time, tiny) ----------------
__global__ __launch_bounds__(256) void wcvt(const float* __restrict__ Wq,
                                            const float* __restrict__ Wk,
                                            const float* __restrict__ Wv)
{
    __shared__ float Wt[64][65];
    const float* W = (blockIdx.y == 0) ? Wk : (blockIdx.y == 1 ? Wq : Wv);
    const int tid = threadIdx.x, k0 = blockIdx.x * 64;
    #pragma unroll
    for (int i = 0; i < 4; i++) {
        int idx = tid + 256 * i;
        int rr = idx >> 4, c4 = (idx & 15) * 4;
        float4 v = *(const float4*)&W[(size_t)(k0 + rr) * DD + c4];
        Wt[rr][c4] = v.x; Wt[rr][c4 + 1] = v.y;
        Wt[rr][c4 + 2] = v.z; Wt[rr][c4 + 3] = v.w;
    }
    __syncthreads();
    int n = tid >> 2, kk = (tid & 3) * 16;
    uint32_t u[8];
    #pragma unroll
    for (int j = 0; j < 8; j++)
        u[j] = packh2(Wt[kk + 2 * j][n], Wt[kk + 2 * j + 1][n]);
    __half* dst = &g_Wt[(size_t)(blockIdx.y * 64 + n) * EE + k0 + kk];
    *(uint4*)dst = *(uint4*)u;
    *(uint4*)(dst + 8) = *(uint4*)(u + 4);
}

// ---------------- fused QKV projection, fp16 mma ----------------
__global__ __launch_bounds__(256) void proj_f16(
    const float* __restrict__ x,
    const float* __restrict__ bq, const float* __restrict__ bk,
    const float* __restrict__ bv)
{
    __shared__ __align__(16) __half Xs[64 * 72];
    __shared__ __align__(16) __half Ws[192 * 72];
    const int tid = threadIdx.x, lane = tid & 31, wid = tid >> 5;
    const int wg = wid & 3, half = wid >> 2;
    const int r = lane >> 2, q = lane & 3;
    const int m0 = blockIdx.x * 64;

    float acc[12][4];
    #pragma unroll
    for (int i = 0; i < 12; i++)
        #pragma unroll
        for (int j = 0; j < 4; j++) acc[i][j] = 0.f;

    for (int k0 = 0; k0 < EE; k0 += 64) {
        {   // stage X (fp32 -> half)
            int row = tid >> 2, c16 = (tid & 3) * 16;
            const float* xp = &x[(size_t)(m0 + row) * EE + k0 + c16];
            float4 v0 = *(const float4*)xp,       v1 = *(const float4*)(xp + 4);
            float4 v2 = *(const float4*)(xp + 8), v3 = *(const float4*)(xp + 12);
            uint4 u0 = make_uint4(packh2(v0.x, v0.y), packh2(v0.z, v0.w),
                                  packh2(v1.x, v1.y), packh2(v1.z, v1.w));
            uint4 u1 = make_uint4(packh2(v2.x, v2.y), packh2(v2.z, v2.w),
                                  packh2(v3.x, v3.y), packh2(v3.z, v3.w));
            *(uint4*)&Xs[row * 72 + c16] = u0;
            *(uint4*)&Xs[row * 72 + c16 + 8] = u1;
        }
        #pragma unroll
        for (int i = 0; i < 6; i++) {   // stage W via cp.async (half, 24KB)
            int ch = tid + 256 * i;
            int rw = ch >> 3, c8 = (ch & 7) * 8;
            cp16((uint32_t)__cvta_generic_to_shared(&Ws[rw * 72 + c8]),
                 g_Wt + (size_t)rw * EE + k0 + c8);
        }
        asm volatile("cp.async.commit_group;");
        asm volatile("cp.async.wait_group 0;");
        __syncthreads();

        const uint32_t* Xu = (const uint32_t*)Xs;
        const uint32_t* Wu = (const uint32_t*)Ws;
        #pragma unroll
        for (int ks = 0; ks < 4; ks++) {
            uint32_t a[4];
            int ra = 16 * wg + r;
            a[0] = Xu[ra * 36 + 8 * ks + q];
            a[1] = Xu[(ra + 8) * 36 + 8 * ks + q];
            a[2] = Xu[ra * 36 + 8 * ks + 4 + q];
            a[3] = Xu[(ra + 8) * 36 + 8 * ks + 4 + q];
            #pragma unroll
            for (int nt = 0; nt < 12; nt++) {
                int n0 = (12 * half + nt) * 8 + r;
                mma_f16(acc[nt], a, Wu[n0 * 36 + 8 * ks + q],
                        Wu[n0 * 36 + 8 * ks + 4 + q]);
            }
        }
        __syncthreads();
    }

    #pragma unroll
    for (int nt = 0; nt < 12; nt++) {
        int ng = (12 * half + nt) * 8 + 2 * q;
        int blk = ng >> 6, nn = ng & 63;
        const float* bias = (blk == 0) ? bk : (blk == 1 ? bq : bv);
        float b0v = bias[nn], b1v = bias[nn + 1];
        int m = m0 + 16 * wg + r;
        float v00 = acc[nt][0] + b0v, v01 = acc[nt][1] + b1v;
        float v10 = acc[nt][2] + b0v, v11 = acc[nt][3] + b1v;
        if (blk == 0) {
            *(uint32_t*)&g_q[(size_t)m * DD + nn] = packh2(v00 * .125f, v01 * .125f);
            *(uint32_t*)&g_q[(size_t)(m + 8) * DD + nn] = packh2(v10 * .125f, v11 * .125f);
        } else if (blk == 1) {
            *(uint32_t*)&g_k[(size_t)m * DD + nn]       = packh2(v00, v01);
            *(uint32_t*)&g_k[(size_t)(m + 8) * DD + nn] = packh2(v10, v11);
        } else {
            int bb = m >> 11, s = m & (SS - 1);
            size_t base = ((size_t)bb * DD + nn) * SS + s;
            g_vt[base]          = __float2half(v00);
            g_vt[base + SS]     = __float2half(v01);
            g_vt[base + 8]      = __float2half(v10);
            g_vt[base + SS + 8] = __float2half(v11);
        }
    }
}

// ---------------- flash phase A: chunk of <=4 KV tiles -> partial ----------------
#define KH 72
#define OSTR 68
__global__ __launch_bounds__(256) void flash_part()
{
    __shared__ __align__(16) char smraw[2 * 64 * KH * 2 * 2 + 1024];
    __half* Kt = (__half*)smraw;
    __half* Vt = Kt + 2 * 64 * KH;
    float* mlb = (float*)(smraw + 2 * (2 * 64 * KH) * 2);
    float* Of  = (float*)smraw;

    const int ck = blockIdx.x, qt = blockIdx.y, b = blockIdx.z;
    const int T = qt + 1, t0 = ck * 4;
    if (t0 >= T) return;
    const int t1 = min(t0 + 4, T), nloc = t1 - t0, NSl = (nloc + 1) >> 1;

    const int tid = threadIdx.x, lane = tid & 31, wid = tid >> 5;
    const int wg = wid & 3, g = wid >> 2;
    const int r = lane >> 2, q = lane & 3;
    const int q0 = qt * 64, rA = 16 * wg + r;

    const __half* gq = g_q + (size_t)(b * SS + q0 + 16 * wg) * DD;
    const __half* gk = g_k + (size_t)b * SS * DD;
    const __half* gv = g_vt + (size_t)b * DD * SS;

    uint32_t qa[4][4];
    #pragma unroll
    for (int ks = 0; ks < 4; ks++) {
        int c0 = 16 * ks + 2 * q;
        qa[ks][0] = *(const uint32_t*)&gq[(size_t)r * DD + c0];
        qa[ks][1] = *(const uint32_t*)&gq[(size_t)(r + 8) * DD + c0];
        qa[ks][2] = *(const uint32_t*)&gq[(size_t)r * DD + c0 + 8];
        qa[ks][3] = *(const uint32_t*)&gq[(size_t)(r + 8) * DD + c0 + 8];
    }

    float o[8][4];
    #pragma unroll
    for (int i = 0; i < 8; i++)
        #pragma unroll
        for (int j = 0; j < 4; j++) o[i][j] = 0.f;
    float m0r = -1e30f, m1r = -1e30f, l0r = 0.f, l1r = 0.f;

    for (int si = 0; si < NSl; si++) {
        if (si > 0) __syncthreads();
        #pragma unroll
        for (int tt = 0; tt < 2; tt++) {
            int tl = 2 * si + tt;
            if (tl < nloc) {
                int k0c = (t0 + tl) * 64;
                #pragma unroll
                for (int i = 0; i < 2; i++) {
                    int idx = tid + i * 256;
                    int row = idx >> 3, c8 = (idx & 7) * 8;
                    cp16((uint32_t)__cvta_generic_to_shared(
                             &Kt[(tt * 64 + row) * KH + c8]),
                         gk + (size_t)(k0c + row) * DD + c8);
                    cp16((uint32_t)__cvta_generic_to_shared(
                             &Vt[(tt * 64 + row) * KH + c8]),
                         gv + (size_t)row * SS + k0c + c8);
                }
            }
        }
        asm volatile("cp.async.commit_group;");
        asm volatile("cp.async.wait_group 0;");
        __syncthreads();

        int tl = 2 * si + g;
        if (tl < nloc) {
            int gt = t0 + tl;
            const __half* KD = Kt + g * 64 * KH;
            const __half* VD = Vt + g * 64 * KH;

            float s[8][4];
            #pragma unroll
            for (int i = 0; i < 8; i++)
                #pragma unroll
                for (int j = 0; j < 4; j++) s[i][j] = 0.f;
            #pragma unroll
            for (int ks = 0; ks < 4; ks++)
                #pragma unroll
                for (int nt = 0; nt < 8; nt++) {
                    uint32_t b0 = *(const uint32_t*)&KD[(8 * nt + r) * KH + 16 * ks + 2 * q];
                    uint32_t b1 = *(const uint32_t*)&KD[(8 * nt + r) * KH + 16 * ks + 8 + 2 * q];
                    mma_f16(s[nt], qa[ks], b0, b1);
                }

            if (gt == qt) {
                int rB = rA + 8;
                #pragma unroll
                for (int nt = 0; nt < 8; nt++) {
                    int c0 = 8 * nt + 2 * q;
                    if (c0     > rA) s[nt][0] = -1e30f;
                    if (c0 + 1 > rA) s[nt][1] = -1e30f;
                    if (c0     > rB) s[nt][2] = -1e30f;
                    if (c0 + 1 > rB) s[nt][3] = -1e30f;
                }
            }

            float pm0 = -1e30f, pm1 = -1e30f;
            #pragma unroll
            for (int nt = 0; nt < 8; nt++) {
                pm0 = fmaxf(pm0, fmaxf(s[nt][0], s[nt][1]));
                pm1 = fmaxf(pm1, fmaxf(s[nt][2], s[nt][3]));
            }
            pm0 = fmaxf(pm0, __shfl_xor_sync(~0u, pm0, 1));
            pm0 = fmaxf(pm0, __shfl_xor_sync(~0u, pm0, 2));
            pm1 = fmaxf(pm1, __shfl_xor_sync(~0u, pm1, 1));
            pm1 = fmaxf(pm1, __shfl_xor_sync(~0u, pm1, 2));
            float mn0 = fmaxf(m0r, pm0), mn1 = fmaxf(m1r, pm1);
            float c0f = __expf(m0r - mn0), c1f = __expf(m1r - mn1);
            m0r = mn0; m1r = mn1;
            float su0 = 0.f, su1 = 0.f;
            #pragma unroll
            for (int nt = 0; nt < 8; nt++) {
                s[nt][0] = __expf(s[nt][0] - m0r);
                s[nt][1] = __expf(s[nt][1] - m0r);
                s[nt][2] = __expf(s[nt][2] - m1r);
                s[nt][3] = __expf(s[nt][3] - m1r);
                su0 += s[nt][0] + s[nt][1];
                su1 += s[nt][2] + s[nt][3];
            }
            su0 += __shfl_xor_sync(~0u, su0, 1);
            su0 += __shfl_xor_sync(~0u, su0, 2);
            su1 += __shfl_xor_sync(~0u, su1, 1);
            su1 += __shfl_xor_sync(~0u, su1, 2);
            l0r = l0r * c0f + su0;  l1r = l1r * c1f + su1;
            #pragma unroll
            for (int nt = 0; nt < 8; nt++) {
                o[nt][0] *= c0f; o[nt][1] *= c0f;
                o[nt][2] *= c1f; o[nt][3] *= c1f;
            }
            #pragma unroll
            for (int t = 0; t < 4; t++) {
                uint32_t pa[4];
                pa[0] = packh2(s[2 * t][0],     s[2 * t][1]);
                pa[1] = packh2(s[2 * t][2],     s[2 * t][3]);
                pa[2] = packh2(s[2 * t + 1][0], s[2 * t + 1][1]);
                pa[3] = packh2(s[2 * t + 1][2], s[2 * t + 1][3]);
                #pragma unroll
                for (int nt = 0; nt < 8; nt++) {
                    uint32_t b0 = *(const uint32_t*)&VD[(8 * nt + r) * KH + 16 * t + 2 * q];
                    uint32_t b1 = *(const uint32_t*)&VD[(8 * nt + r) * KH + 16 * t + 8 + 2 * q];
                    mma_f16(o[nt], pa, b0, b1);
                }
            }
        }
    }

    // merge two groups, write partial (unnormalized O, M, L)
    __syncthreads();
    if (q == 0) {
        mlb[g * 64 + rA]           = m0r;
        mlb[g * 64 + rA + 8]       = m1r;
        mlb[128 + g * 64 + rA]     = l0r;
        mlb[128 + g * 64 + rA + 8] = l1r;
    }
    __syncthreads();
    int og = 1 - g;
    float mo0 = mlb[og * 64 + rA],       mo1 = mlb[og * 64 + rA + 8];
    float lo0 = mlb[128 + og * 64 + rA], lo1 = mlb[128 + og * 64 + rA + 8];
    float M0 = fmaxf(m0r, mo0), M1 = fmaxf(m1r, mo1);
    float sc0 = __expf(m0r - M0), sc1 = __expf(m1r - M1);
    float L0 = l0r * sc0 + lo0 * __expf(mo0 - M0);
    float L1 = l1r * sc1 + lo1 * __expf(mo1 - M1);
    __syncthreads();
    if (g == 1) {
        #pragma unroll
        for (int nt = 0; nt < 8; nt++) {
            int cc = 8 * nt + 2 * q;
            *(float2*)&Of[rA * OSTR + cc] =
                make_float2(o[nt][0] * sc0, o[nt][1] * sc0);
            *(float2*)&Of[(rA + 8) * OSTR + cc] =
                make_float2(o[nt][2] * sc1, o[nt][3] * sc1);
        }
    }
    __syncthreads();
    size_t pb = ((size_t)(b * 32 + qt) * 8 + ck);
    if (g == 0) {
        float* op = &g_part[pb * 4096];
        #pragma unroll
        for (int nt = 0; nt < 8; nt++) {
            int cc = 8 * nt + 2 * q;
            float2 s0 = *(float2*)&Of[rA * OSTR + cc];
            float2 s1 = *(float2*)&Of[(rA + 8) * OSTR + cc];
            *(float2*)&op[rA * 64 + cc] =
                make_float2(o[nt][0] * sc0 + s0.x, o[nt][1] * sc0 + s0.y);
            *(float2*)&op[(rA + 8) * 64 + cc] =
                make_float2(o[nt][2] * sc1 + s1.x, o[nt][3] * sc1 + s1.y);
        }
        if (q == 0) {
            float* mp = &g_ml[pb * 128];
            mp[rA] = M0;  mp[rA + 8] = M1;
            mp[64 + rA] = L0;  mp[64 + rA + 8] = L1;
        }
    }
}

// ---------------- flash phase B: merge chunks ----------------
__global__ __launch_bounds__(256) void flash_merge(float* __restrict__ out)
{
    const int qt = blockIdx.x, b = blockIdx.y;
    const int T = qt + 1, nc = (T + 3) >> 2;
    const int row = threadIdx.x >> 2, c0 = (threadIdx.x & 3) * 16;
    size_t pb = (size_t)(b * 32 + qt) * 8;

    float mv[8], lv[8], M = -1e30f;
    for (int c = 0; c < nc; c++) {
        mv[c] = g_ml[(pb + c) * 128 + row];
        lv[c] = g_ml[(pb + c) * 128 + 64 + row];
        M = fmaxf(M, mv[c]);
    }
    float L = 0.f, acc[16];
    #pragma unroll
    for (int j = 0; j < 16; j++) acc[j] = 0.f;
    for (int c = 0; c < nc; c++) {
        float w = __expf(mv[c] - M);
        L += lv[c] * w;
        const float* p = &g_part[(pb + c) * 4096 + row * 64 + c0];
        #pragma unroll
        for (int j = 0; j < 4; j++) {
            float4 v = *(const float4*)&p[4 * j];
            acc[4 * j]     += w * v.x;  acc[4 * j + 1] += w * v.y;
            acc[4 * j + 2] += w * v.z;  acc[4 * j + 3] += w * v.w;
        }
    }
    float inv = 1.f / L;
    float* ob = out + ((size_t)(b * SS) + qt * 64 + row) * DD + c0;
    #pragma unroll
    for (int j = 0; j < 4; j++)
        *(float4*)&ob[4 * j] = make_float4(acc[4 * j] * inv, acc[4 * j + 1] * inv,
                                           acc[4 * j + 2] * inv, acc[4 * j + 3] * inv);
}

extern "C" void kernel_launch(void* const* d_in, const int* in_sizes, int n_in,
                              void* d_out, int out_size)
{
    const float* x  = (const float*)d_in[0];
    const float* Wq = (const float*)d_in[2];
    const float* bq = (const float*)d_in[3];
    const float* Wk = (const float*)d_in[4];
    const float* bk = (const float*)d_in[5];
    const float* Wv = (const float*)d_in[6];
    const float* bv = (const float*)d_in[7];
    float* out = (float*)d_out;

    wcvt<<<dim3(16, 3), 256>>>(Wq, Wk, Wv);
    proj_f16<<<BB * SS / 64, 256>>>(x, bq, bk, bv);
    flash_part<<<dim3(8, 32, BB), 256>>>();
    flash_merge<<<dim3(32, BB), 256>>>(out);
}

// round 7
// speedup vs baseline: 5.0250x; 1.0198x over previous
#include <cuda_runtime.h>
#include <cuda_fp16.h>
#include <cstdint>

#define BB 4
#define SS 2048
#define EE 1024
#define DD 64

__device__ __align__(16) __half g_q [BB * SS * DD];   // scaled 1/8
__device__ __align__(16) __half g_k [BB * SS * DD];
__device__ __align__(16) __half g_vt[BB * DD * SS];   // [b][d][s]
__device__ __align__(16) __half g_Wt[192 * EE];
__device__ float g_part[BB * 32 * 8 * 64 * 64];
__device__ float g_ml  [BB * 32 * 8 * 128];

__device__ __forceinline__ uint32_t packh2(float a, float b) {
    __half2 h = __floats2half2_rn(a, b); return *(uint32_t*)&h;
}
__device__ __forceinline__ void mma_f16(float c[4], const uint32_t a[4],
                                        uint32_t b0, uint32_t b1) {
    asm volatile("mma.sync.aligned.m16n8k16.row.col.f32.f16.f16.f32 "
        "{%0,%1,%2,%3},{%4,%5,%6,%7},{%8,%9},{%0,%1,%2,%3};"
        : "+f"(c[0]), "+f"(c[1]), "+f"(c[2]), "+f"(c[3])
        : "r"(a[0]), "r"(a[1]), "r"(a[2]), "r"(a[3]), "r"(b0), "r"(b1));
}
__device__ __forceinline__ void cp16(uint32_t d, const void* s) {
    asm volatile("cp.async.cg.shared.global [%0], [%1], 16;" :: "r"(d), "l"(s));
}

// ---------------- W transpose + fp16 convert ----------------
__global__ __launch_bounds__(256) void wcvt(const float* __restrict__ Wq,
                                            const float* __restrict__ Wk,
                                            const float* __restrict__ Wv)
{
    __shared__ float Wt[64][65];
    const float* W = (blockIdx.y == 0) ? Wk : (blockIdx.y == 1 ? Wq : Wv);
    const int tid = threadIdx.x, k0 = blockIdx.x * 64;
    #pragma unroll
    for (int i = 0; i < 4; i++) {
        int idx = tid + 256 * i;
        int rr = idx >> 4, c4 = (idx & 15) * 4;
        float4 v = *(const float4*)&W[(size_t)(k0 + rr) * DD + c4];
        Wt[rr][c4] = v.x; Wt[rr][c4 + 1] = v.y;
        Wt[rr][c4 + 2] = v.z; Wt[rr][c4 + 3] = v.w;
    }
    __syncthreads();
    int n = tid >> 2, kk = (tid & 3) * 16;
    uint32_t u[8];
    #pragma unroll
    for (int j = 0; j < 8; j++)
        u[j] = packh2(Wt[kk + 2 * j][n], Wt[kk + 2 * j + 1][n]);
    __half* dst = &g_Wt[(size_t)(blockIdx.y * 64 + n) * EE + k0 + kk];
    *(uint4*)dst = *(uint4*)u;
    *(uint4*)(dst + 8) = *(uint4*)(u + 4);
}

// ---------------- fused QKV projection, fp16 mma ----------------
__global__ __launch_bounds__(256) void proj_f16(
    const float* __restrict__ x,
    const float* __restrict__ bq, const float* __restrict__ bk,
    const float* __restrict__ bv)
{
    __shared__ __align__(16) __half Xs[64 * 72];
    __shared__ __align__(16) __half Ws[192 * 72];
    const int tid = threadIdx.x, lane = tid & 31, wid = tid >> 5;
    const int wg = wid & 3, half = wid >> 2;
    const int r = lane >> 2, q = lane & 3;
    const int m0 = blockIdx.x * 64;

    float acc[12][4];
    #pragma unroll
    for (int i = 0; i < 12; i++)
        #pragma unroll
        for (int j = 0; j < 4; j++) acc[i][j] = 0.f;

    for (int k0 = 0; k0 < EE; k0 += 64) {
        #pragma unroll
        for (int i = 0; i < 6; i++) {   // W first: copy overlaps X staging below
            int ch = tid + 256 * i;
            int rw = ch >> 3, c8 = (ch & 7) * 8;
            cp16((uint32_t)__cvta_generic_to_shared(&Ws[rw * 72 + c8]),
                 g_Wt + (size_t)rw * EE + k0 + c8);
        }
        asm volatile("cp.async.commit_group;");
        {   // stage X (fp32 -> half)
            int row = tid >> 2, c16 = (tid & 3) * 16;
            const float* xp = &x[(size_t)(m0 + row) * EE + k0 + c16];
            float4 v0 = *(const float4*)xp,       v1 = *(const float4*)(xp + 4);
            float4 v2 = *(const float4*)(xp + 8), v3 = *(const float4*)(xp + 12);
            uint4 u0 = make_uint4(packh2(v0.x, v0.y), packh2(v0.z, v0.w),
                                  packh2(v1.x, v1.y), packh2(v1.z, v1.w));
            uint4 u1 = make_uint4(packh2(v2.x, v2.y), packh2(v2.z, v2.w),
                                  packh2(v3.x, v3.y), packh2(v3.z, v3.w));
            *(uint4*)&Xs[row * 72 + c16] = u0;
            *(uint4*)&Xs[row * 72 + c16 + 8] = u1;
        }
        asm volatile("cp.async.wait_group 0;");
        __syncthreads();

        const uint32_t* Xu = (const uint32_t*)Xs;
        const uint32_t* Wu = (const uint32_t*)Ws;
        #pragma unroll
        for (int ks = 0; ks < 4; ks++) {
            uint32_t a[4];
            int ra = 16 * wg + r;
            a[0] = Xu[ra * 36 + 8 * ks + q];
            a[1] = Xu[(ra + 8) * 36 + 8 * ks + q];
            a[2] = Xu[ra * 36 + 8 * ks + 4 + q];
            a[3] = Xu[(ra + 8) * 36 + 8 * ks + 4 + q];
            #pragma unroll
            for (int nt = 0; nt < 12; nt++) {
                int n0 = (12 * half + nt) * 8 + r;
                mma_f16(acc[nt], a, Wu[n0 * 36 + 8 * ks + q],
                        Wu[n0 * 36 + 8 * ks + 4 + q]);
            }
        }
        __syncthreads();
    }

    #pragma unroll
    for (int nt = 0; nt < 12; nt++) {
        int ng = (12 * half + nt) * 8 + 2 * q;
        int blk = ng >> 6, nn = ng & 63;
        const float* bias = (blk == 0) ? bk : (blk == 1 ? bq : bv);
        float b0v = bias[nn], b1v = bias[nn + 1];
        int m = m0 + 16 * wg + r;
        float v00 = acc[nt][0] + b0v, v01 = acc[nt][1] + b1v;
        float v10 = acc[nt][2] + b0v, v11 = acc[nt][3] + b1v;
        if (blk == 0) {
            *(uint32_t*)&g_q[(size_t)m * DD + nn] = packh2(v00 * .125f, v01 * .125f);
            *(uint32_t*)&g_q[(size_t)(m + 8) * DD + nn] = packh2(v10 * .125f, v11 * .125f);
        } else if (blk == 1) {
            *(uint32_t*)&g_k[(size_t)m * DD + nn]       = packh2(v00, v01);
            *(uint32_t*)&g_k[(size_t)(m + 8) * DD + nn] = packh2(v10, v11);
        } else {
            int bb = m >> 11, s = m & (SS - 1);
            size_t base = ((size_t)bb * DD + nn) * SS + s;
            g_vt[base]          = __float2half(v00);
            g_vt[base + SS]     = __float2half(v01);
            g_vt[base + 8]      = __float2half(v10);
            g_vt[base + SS + 8] = __float2half(v11);
        }
    }
}

// ---------------- flash phase A ----------------
#define KH 72
#define OSTR 68
#define SM_PART (4 * 64 * KH * 2 * 2 + 1024)   // 74752 B
__global__ __launch_bounds__(256) void flash_part(float* __restrict__ out)
{
    extern __shared__ __align__(16) char smraw[];
    __half* Kt = (__half*)smraw;
    __half* Vt = Kt + 4 * 64 * KH;
    float* mlb = (float*)(smraw + 4 * 64 * KH * 2 * 2);
    float* Of  = (float*)smraw;

    const int ck = blockIdx.x, qt = blockIdx.y, b = blockIdx.z;
    const int T = qt + 1, t0 = ck * 4;
    if (t0 >= T) return;
    const int nloc = min(4, T - t0), nc = (T + 3) >> 2;

    const int tid = threadIdx.x, lane = tid & 31, wid = tid >> 5;
    const int wg = wid & 3, g = wid >> 2;
    const int r = lane >> 2, q = lane & 3;
    const int q0 = qt * 64, rA = 16 * wg + r;

    const __half* gq = g_q + (size_t)(b * SS + q0 + 16 * wg) * DD;
    const __half* gk = g_k + (size_t)b * SS * DD;
    const __half* gv = g_vt + (size_t)b * DD * SS;

    // prefetch all tiles (2 commit groups: tiles {0,1}, {2,3})
    #pragma unroll
    for (int pr = 0; pr < 2; pr++) {
        #pragma unroll
        for (int t2 = 0; t2 < 2; t2++) {
            int tl = pr * 2 + t2;
            if (tl < nloc) {
                int k0c = (t0 + tl) * 64;
                #pragma unroll
                for (int i = 0; i < 2; i++) {
                    int idx = tid + i * 256;
                    int row = idx >> 3, c8 = (idx & 7) * 8;
                    cp16((uint32_t)__cvta_generic_to_shared(
                             &Kt[(tl * 64 + row) * KH + c8]),
                         gk + (size_t)(k0c + row) * DD + c8);
                    cp16((uint32_t)__cvta_generic_to_shared(
                             &Vt[(tl * 64 + row) * KH + c8]),
                         gv + (size_t)row * SS + k0c + c8);
                }
            }
        }
        asm volatile("cp.async.commit_group;");
    }

    uint32_t qa[4][4];
    #pragma unroll
    for (int ks = 0; ks < 4; ks++) {
        int c0 = 16 * ks + 2 * q;
        qa[ks][0] = *(const uint32_t*)&gq[(size_t)r * DD + c0];
        qa[ks][1] = *(const uint32_t*)&gq[(size_t)(r + 8) * DD + c0];
        qa[ks][2] = *(const uint32_t*)&gq[(size_t)r * DD + c0 + 8];
        qa[ks][3] = *(const uint32_t*)&gq[(size_t)(r + 8) * DD + c0 + 8];
    }

    float o[8][4];
    #pragma unroll
    for (int i = 0; i < 8; i++)
        #pragma unroll
        for (int j = 0; j < 4; j++) o[i][j] = 0.f;
    float m0r = -1e30f, m1r = -1e30f, l0r = 0.f, l1r = 0.f;

    #pragma unroll
    for (int si = 0; si < 2; si++) {
        if (2 * si >= nloc) break;
        if (si == 0) asm volatile("cp.async.wait_group 1;");
        else         asm volatile("cp.async.wait_group 0;");
        __syncthreads();

        int tl = 2 * si + g;
        if (tl < nloc) {
            int gt = t0 + tl;
            const __half* KD = Kt + tl * 64 * KH;
            const __half* VD = Vt + tl * 64 * KH;

            float s[8][4];
            #pragma unroll
            for (int i = 0; i < 8; i++)
                #pragma unroll
                for (int j = 0; j < 4; j++) s[i][j] = 0.f;
            #pragma unroll
            for (int ks = 0; ks < 4; ks++)
                #pragma unroll
                for (int nt = 0; nt < 8; nt++) {
                    uint32_t b0 = *(const uint32_t*)&KD[(8 * nt + r) * KH + 16 * ks + 2 * q];
                    uint32_t b1 = *(const uint32_t*)&KD[(8 * nt + r) * KH + 16 * ks + 8 + 2 * q];
                    mma_f16(s[nt], qa[ks], b0, b1);
                }

            if (gt == qt) {
                int rB = rA + 8;
                #pragma unroll
                for (int nt = 0; nt < 8; nt++) {
                    int c0 = 8 * nt + 2 * q;
                    if (c0     > rA) s[nt][0] = -1e30f;
                    if (c0 + 1 > rA) s[nt][1] = -1e30f;
                    if (c0     > rB) s[nt][2] = -1e30f;
                    if (c0 + 1 > rB) s[nt][3] = -1e30f;
                }
            }

            float pm0 = -1e30f, pm1 = -1e30f;
            #pragma unroll
            for (int nt = 0; nt < 8; nt++) {
                pm0 = fmaxf(pm0, fmaxf(s[nt][0], s[nt][1]));
                pm1 = fmaxf(pm1, fmaxf(s[nt][2], s[nt][3]));
            }
            pm0 = fmaxf(pm0, __shfl_xor_sync(~0u, pm0, 1));
            pm0 = fmaxf(pm0, __shfl_xor_sync(~0u, pm0, 2));
            pm1 = fmaxf(pm1, __shfl_xor_sync(~0u, pm1, 1));
            pm1 = fmaxf(pm1, __shfl_xor_sync(~0u, pm1, 2));
            float mn0 = fmaxf(m0r, pm0), mn1 = fmaxf(m1r, pm1);
            float c0f = __expf(m0r - mn0), c1f = __expf(m1r - mn1);
            m0r = mn0; m1r = mn1;
            float su0 = 0.f, su1 = 0.f;
            #pragma unroll
            for (int nt = 0; nt < 8; nt++) {
                s[nt][0] = __expf(s[nt][0] - m0r);
                s[nt][1] = __expf(s[nt][1] - m0r);
                s[nt][2] = __expf(s[nt][2] - m1r);
                s[nt][3] = __expf(s[nt][3] - m1r);
                su0 += s[nt][0] + s[nt][1];
                su1 += s[nt][2] + s[nt][3];
            }
            su0 += __shfl_xor_sync(~0u, su0, 1);
            su0 += __shfl_xor_sync(~0u, su0, 2);
            su1 += __shfl_xor_sync(~0u, su1, 1);
            su1 += __shfl_xor_sync(~0u, su1, 2);
            l0r = l0r * c0f + su0;  l1r = l1r * c1f + su1;
            #pragma unroll
            for (int nt = 0; nt < 8; nt++) {
                o[nt][0] *= c0f; o[nt][1] *= c0f;
                o[nt][2] *= c1f; o[nt][3] *= c1f;
            }
            #pragma unroll
            for (int t = 0; t < 4; t++) {
                uint32_t pa[4];
                pa[0] = packh2(s[2 * t][0],     s[2 * t][1]);
                pa[1] = packh2(s[2 * t][2],     s[2 * t][3]);
                pa[2] = packh2(s[2 * t + 1][0], s[2 * t + 1][1]);
                pa[3] = packh2(s[2 * t + 1][2], s[2 * t + 1][3]);
                #pragma unroll
                for (int nt = 0; nt < 8; nt++) {
                    uint32_t b0 = *(const uint32_t*)&VD[(8 * nt + r) * KH + 16 * t + 2 * q];
                    uint32_t b1 = *(const uint32_t*)&VD[(8 * nt + r) * KH + 16 * t + 8 + 2 * q];
                    mma_f16(o[nt], pa, b0, b1);
                }
            }
        }
    }

    // merge groups
    __syncthreads();
    if (q == 0) {
        mlb[g * 64 + rA]           = m0r;
        mlb[g * 64 + rA + 8]       = m1r;
        mlb[128 + g * 64 + rA]     = l0r;
        mlb[128 + g * 64 + rA + 8] = l1r;
    }
    __syncthreads();
    int og = 1 - g;
    float mo0 = mlb[og * 64 + rA],       mo1 = mlb[og * 64 + rA + 8];
    float lo0 = mlb[128 + og * 64 + rA], lo1 = mlb[128 + og * 64 + rA + 8];
    float M0 = fmaxf(m0r, mo0), M1 = fmaxf(m1r, mo1);
    float sc0 = __expf(m0r - M0), sc1 = __expf(m1r - M1);
    float L0 = l0r * sc0 + lo0 * __expf(mo0 - M0);
    float L1 = l1r * sc1 + lo1 * __expf(mo1 - M1);
    __syncthreads();
    if (g == 1) {
        #pragma unroll
        for (int nt = 0; nt < 8; nt++) {
            int cc = 8 * nt + 2 * q;
            *(float2*)&Of[rA * OSTR + cc] =
                make_float2(o[nt][0] * sc0, o[nt][1] * sc0);
            *(float2*)&Of[(rA + 8) * OSTR + cc] =
                make_float2(o[nt][2] * sc1, o[nt][3] * sc1);
        }
    }
    __syncthreads();
    if (g == 0) {
        if (nc == 1) {   // single chunk: write final result directly
            float* ob = out + (size_t)(b * SS + q0) * DD;
            float i0 = 1.f / L0, i1 = 1.f / L1;
            #pragma unroll
            for (int nt = 0; nt < 8; nt++) {
                int cc = 8 * nt + 2 * q;
                float2 s0 = *(float2*)&Of[rA * OSTR + cc];
                float2 s1 = *(float2*)&Of[(rA + 8) * OSTR + cc];
                *(float2*)&ob[(size_t)rA * DD + cc] = make_float2(
                    (o[nt][0] * sc0 + s0.x) * i0, (o[nt][1] * sc0 + s0.y) * i0);
                *(float2*)&ob[(size_t)(rA + 8) * DD + cc] = make_float2(
                    (o[nt][2] * sc1 + s1.x) * i1, (o[nt][3] * sc1 + s1.y) * i1);
            }
        } else {
            size_t pb = (size_t)(b * 32 + qt) * 8 + ck;
            float* op = &g_part[pb * 4096];
            #pragma unroll
            for (int nt = 0; nt < 8; nt++) {
                int cc = 8 * nt + 2 * q;
                float2 s0 = *(float2*)&Of[rA * OSTR + cc];
                float2 s1 = *(float2*)&Of[(rA + 8) * OSTR + cc];
                *(float2*)&op[rA * 64 + cc] =
                    make_float2(o[nt][0] * sc0 + s0.x, o[nt][1] * sc0 + s0.y);
                *(float2*)&op[(rA + 8) * 64 + cc] =
                    make_float2(o[nt][2] * sc1 + s1.x, o[nt][3] * sc1 + s1.y);
            }
            if (q == 0) {
                float* mp = &g_ml[pb * 128];
                mp[rA] = M0;  mp[rA + 8] = M1;
                mp[64 + rA] = L0;  mp[64 + rA + 8] = L1;
            }
        }
    }
}

// ---------------- flash phase B: one warp per row ----------------
__global__ __launch_bounds__(256) void flash_merge(float* __restrict__ out)
{
    const int gr = blockIdx.x * 8 + (threadIdx.x >> 5);
    const int lane = threadIdx.x & 31;
    const int b = gr >> 11, s = gr & (SS - 1), qt = s >> 6;
    const int nc = (qt + 4) >> 2;
    if (nc < 2) return;   // handled directly by flash_part
    const int row = s & 63;
    const size_t pb = (size_t)(b * 32 + qt) * 8;

    float mv[8], lv[8], M = -1e30f;
    for (int c = 0; c < nc; c++) {
        mv[c] = g_ml[(pb + c) * 128 + row];
        lv[c] = g_ml[(pb + c) * 128 + 64 + row];
        M = fmaxf(M, mv[c]);
    }
    float L = 0.f;
    float2 acc = make_float2(0.f, 0.f);
    for (int c = 0; c < nc; c++) {
        float w = __expf(mv[c] - M);
        L += lv[c] * w;
        float2 v = *(const float2*)&g_part[(pb + c) * 4096 + row * 64 + lane * 2];
        acc.x += w * v.x;  acc.y += w * v.y;
    }
    float inv = 1.f / L;
    *(float2*)&out[(size_t)gr * DD + lane * 2] =
        make_float2(acc.x * inv, acc.y * inv);
}

extern "C" void kernel_launch(void* const* d_in, const int* in_sizes, int n_in,
                              void* d_out, int out_size)
{
    const float* x  = (const float*)d_in[0];
    const float* Wq = (const float*)d_in[2];
    const float* bq = (const float*)d_in[3];
    const float* Wk = (const float*)d_in[4];
    const float* bk = (const float*)d_in[5];
    const float* Wv = (const float*)d_in[6];
    const float* bv = (const float*)d_in[7];
    float* out = (float*)d_out;

    cudaFuncSetAttribute(flash_part,
                         cudaFuncAttributeMaxDynamicSharedMemorySize, SM_PART);
    wcvt<<<dim3(16, 3), 256>>>(Wq, Wk, Wv);
    proj_f16<<<BB * SS / 64, 256>>>(x, bq, bk, bv);
    flash_part<<<dim3(8, 32, BB), 256, SM_PART>>>(out);
    flash_merge<<<BB * SS / 8, 256>>>(out);
}

// round 8
// speedup vs baseline: 5.1388x; 1.0226x over previous
#include <cuda_runtime.h>
#include <cuda_fp16.h>
#include <cstdint>

#define BB 4
#define SS 2048
#define EE 1024
#define DD 64

__device__ __align__(16) __half g_q [BB * SS * DD];   // scaled 1/8
__device__ __align__(16) __half g_k [BB * SS * DD];
__device__ __align__(16) __half g_vt[BB * DD * SS];   // [b][d][s]
__device__ __align__(16) __half g_Wt[192 * EE];
__device__ float g_part[BB * 32 * 8 * 64 * 64];
__device__ float g_ml  [BB * 32 * 8 * 128];

__device__ __forceinline__ uint32_t packh2(float a, float b) {
    __half2 h = __floats2half2_rn(a, b); return *(uint32_t*)&h;
}
__device__ __forceinline__ void mma_f16(float c[4], const uint32_t a[4],
                                        uint32_t b0, uint32_t b1) {
    asm volatile("mma.sync.aligned.m16n8k16.row.col.f32.f16.f16.f32 "
        "{%0,%1,%2,%3},{%4,%5,%6,%7},{%8,%9},{%0,%1,%2,%3};"
        : "+f"(c[0]), "+f"(c[1]), "+f"(c[2]), "+f"(c[3])
        : "r"(a[0]), "r"(a[1]), "r"(a[2]), "r"(a[3]), "r"(b0), "r"(b1));
}
__device__ __forceinline__ void cp16(uint32_t d, const void* s) {
    asm volatile("cp.async.cg.shared.global [%0], [%1], 16;" :: "r"(d), "l"(s));
}

// ---------------- W transpose + fp16 convert ----------------
__global__ __launch_bounds__(256) void wcvt(const float* __restrict__ Wq,
                                            const float* __restrict__ Wk,
                                            const float* __restrict__ Wv)
{
    __shared__ float Wt[64][65];
    const float* W = (blockIdx.y == 0) ? Wk : (blockIdx.y == 1 ? Wq : Wv);
    const int tid = threadIdx.x, k0 = blockIdx.x * 64;
    #pragma unroll
    for (int i = 0; i < 4; i++) {
        int idx = tid + 256 * i;
        int rr = idx >> 4, c4 = (idx & 15) * 4;
        float4 v = *(const float4*)&W[(size_t)(k0 + rr) * DD + c4];
        Wt[rr][c4] = v.x; Wt[rr][c4 + 1] = v.y;
        Wt[rr][c4 + 2] = v.z; Wt[rr][c4 + 3] = v.w;
    }
    __syncthreads();
    int n = tid >> 2, kk = (tid & 3) * 16;
    uint32_t u[8];
    #pragma unroll
    for (int j = 0; j < 8; j++)
        u[j] = packh2(Wt[kk + 2 * j][n], Wt[kk + 2 * j + 1][n]);
    __half* dst = &g_Wt[(size_t)(blockIdx.y * 64 + n) * EE + k0 + kk];
    *(uint4*)dst = *(uint4*)u;
    *(uint4*)(dst + 8) = *(uint4*)(u + 4);
}

// ---------------- fused QKV projection, fp16 mma ----------------
__global__ __launch_bounds__(256) void proj_f16(
    const float* __restrict__ x,
    const float* __restrict__ bq, const float* __restrict__ bk,
    const float* __restrict__ bv)
{
    __shared__ __align__(16) __half Xs[64 * 72];
    __shared__ __align__(16) __half Ws[192 * 72];
    const int tid = threadIdx.x, lane = tid & 31, wid = tid >> 5;
    const int wg = wid & 3, half = wid >> 2;
    const int r = lane >> 2, q = lane & 3;
    const int m0 = blockIdx.x * 64;

    float acc[12][4];
    #pragma unroll
    for (int i = 0; i < 12; i++)
        #pragma unroll
        for (int j = 0; j < 4; j++) acc[i][j] = 0.f;

    for (int k0 = 0; k0 < EE; k0 += 64) {
        #pragma unroll
        for (int i = 0; i < 6; i++) {   // W first: copy overlaps X staging below
            int ch = tid + 256 * i;
            int rw = ch >> 3, c8 = (ch & 7) * 8;
            cp16((uint32_t)__cvta_generic_to_shared(&Ws[rw * 72 + c8]),
                 g_Wt + (size_t)rw * EE + k0 + c8);
        }
        asm volatile("cp.async.commit_group;");
        {   // stage X (fp32 -> half)
            int row = tid >> 2, c16 = (tid & 3) * 16;
            const float* xp = &x[(size_t)(m0 + row) * EE + k0 + c16];
            float4 v0 = *(const float4*)xp,       v1 = *(const float4*)(xp + 4);
            float4 v2 = *(const float4*)(xp + 8), v3 = *(const float4*)(xp + 12);
            uint4 u0 = make_uint4(packh2(v0.x, v0.y), packh2(v0.z, v0.w),
                                  packh2(v1.x, v1.y), packh2(v1.z, v1.w));
            uint4 u1 = make_uint4(packh2(v2.x, v2.y), packh2(v2.z, v2.w),
                                  packh2(v3.x, v3.y), packh2(v3.z, v3.w));
            *(uint4*)&Xs[row * 72 + c16] = u0;
            *(uint4*)&Xs[row * 72 + c16 + 8] = u1;
        }
        asm volatile("cp.async.wait_group 0;");
        __syncthreads();

        const uint32_t* Xu = (const uint32_t*)Xs;
        const uint32_t* Wu = (const uint32_t*)Ws;
        #pragma unroll
        for (int ks = 0; ks < 4; ks++) {
            uint32_t a[4];
            int ra = 16 * wg + r;
            a[0] = Xu[ra * 36 + 8 * ks + q];
            a[1] = Xu[(ra + 8) * 36 + 8 * ks + q];
            a[2] = Xu[ra * 36 + 8 * ks + 4 + q];
            a[3] = Xu[(ra + 8) * 36 + 8 * ks + 4 + q];
            #pragma unroll
            for (int nt = 0; nt < 12; nt++) {
                int n0 = (12 * half + nt) * 8 + r;
                mma_f16(acc[nt], a, Wu[n0 * 36 + 8 * ks + q],
                        Wu[n0 * 36 + 8 * ks + 4 + q]);
            }
        }
        __syncthreads();
    }

    #pragma unroll
    for (int nt = 0; nt < 12; nt++) {
        int ng = (12 * half + nt) * 8 + 2 * q;
        int blk = ng >> 6, nn = ng & 63;
        const float* bias = (blk == 0) ? bk : (blk == 1 ? bq : bv);
        float b0v = bias[nn], b1v = bias[nn + 1];
        int m = m0 + 16 * wg + r;
        float v00 = acc[nt][0] + b0v, v01 = acc[nt][1] + b1v;
        float v10 = acc[nt][2] + b0v, v11 = acc[nt][3] + b1v;
        if (blk == 0) {
            *(uint32_t*)&g_q[(size_t)m * DD + nn] = packh2(v00 * .125f, v01 * .125f);
            *(uint32_t*)&g_q[(size_t)(m + 8) * DD + nn] = packh2(v10 * .125f, v11 * .125f);
        } else if (blk == 1) {
            *(uint32_t*)&g_k[(size_t)m * DD + nn]       = packh2(v00, v01);
            *(uint32_t*)&g_k[(size_t)(m + 8) * DD + nn] = packh2(v10, v11);
        } else {
            int bb = m >> 11, s = m & (SS - 1);
            size_t base = ((size_t)bb * DD + nn) * SS + s;
            g_vt[base]          = __float2half(v00);
            g_vt[base + SS]     = __float2half(v01);
            g_vt[base + 8]      = __float2half(v10);
            g_vt[base + SS + 8] = __float2half(v11);
        }
    }
}

// ---------------- flash phase A ----------------
#define KH 72
#define OSTR 68
#define SM_PART (4 * 64 * KH * 2 * 2 + 1024)   // 74752 B
__global__ __launch_bounds__(256) void flash_part(float* __restrict__ out)
{
    extern __shared__ __align__(16) char smraw[];
    __half* Kt = (__half*)smraw;
    __half* Vt = Kt + 4 * 64 * KH;
    float* mlb = (float*)(smraw + 4 * 64 * KH * 2 * 2);
    float* Of  = (float*)smraw;

    const int ck = blockIdx.x, qt = blockIdx.y, b = blockIdx.z;
    const int T = qt + 1, t0 = ck * 4;
    if (t0 >= T) return;
    const int nloc = min(4, T - t0), nc = (T + 3) >> 2;

    const int tid = threadIdx.x, lane = tid & 31, wid = tid >> 5;
    const int wg = wid & 3, g = wid >> 2;
    const int r = lane >> 2, q = lane & 3;
    const int q0 = qt * 64, rA = 16 * wg + r;

    const __half* gq = g_q + (size_t)(b * SS + q0 + 16 * wg) * DD;
    const __half* gk = g_k + (size_t)b * SS * DD;
    const __half* gv = g_vt + (size_t)b * DD * SS;

    // prefetch all tiles (2 commit groups: tiles {0,1}, {2,3})
    #pragma unroll
    for (int pr = 0; pr < 2; pr++) {
        #pragma unroll
        for (int t2 = 0; t2 < 2; t2++) {
            int tl = pr * 2 + t2;
            if (tl < nloc) {
                int k0c = (t0 + tl) * 64;
                #pragma unroll
                for (int i = 0; i < 2; i++) {
                    int idx = tid + i * 256;
                    int row = idx >> 3, c8 = (idx & 7) * 8;
                    cp16((uint32_t)__cvta_generic_to_shared(
                             &Kt[(tl * 64 + row) * KH + c8]),
                         gk + (size_t)(k0c + row) * DD + c8);
                    cp16((uint32_t)__cvta_generic_to_shared(
                             &Vt[(tl * 64 + row) * KH + c8]),
                         gv + (size_t)row * SS + k0c + c8);
                }
            }
        }
        asm volatile("cp.async.commit_group;");
    }

    uint32_t qa[4][4];
    #pragma unroll
    for (int ks = 0; ks < 4; ks++) {
        int c0 = 16 * ks + 2 * q;
        qa[ks][0] = *(const uint32_t*)&gq[(size_t)r * DD + c0];
        qa[ks][1] = *(const uint32_t*)&gq[(size_t)(r + 8) * DD + c0];
        qa[ks][2] = *(const uint32_t*)&gq[(size_t)r * DD + c0 + 8];
        qa[ks][3] = *(const uint32_t*)&gq[(size_t)(r + 8) * DD + c0 + 8];
    }

    float o[8][4];
    #pragma unroll
    for (int i = 0; i < 8; i++)
        #pragma unroll
        for (int j = 0; j < 4; j++) o[i][j] = 0.f;
    float m0r = -1e30f, m1r = -1e30f, l0r = 0.f, l1r = 0.f;

    #pragma unroll
    for (int si = 0; si < 2; si++) {
        if (2 * si >= nloc) break;
        if (si == 0) asm volatile("cp.async.wait_group 1;");
        else         asm volatile("cp.async.wait_group 0;");
        __syncthreads();

        int tl = 2 * si + g;
        if (tl < nloc) {
            int gt = t0 + tl;
            const __half* KD = Kt + tl * 64 * KH;
            const __half* VD = Vt + tl * 64 * KH;

            float s[8][4];
            #pragma unroll
            for (int i = 0; i < 8; i++)
                #pragma unroll
                for (int j = 0; j < 4; j++) s[i][j] = 0.f;
            #pragma unroll
            for (int ks = 0; ks < 4; ks++)
                #pragma unroll
                for (int nt = 0; nt < 8; nt++) {
                    uint32_t b0 = *(const uint32_t*)&KD[(8 * nt + r) * KH + 16 * ks + 2 * q];
                    uint32_t b1 = *(const uint32_t*)&KD[(8 * nt + r) * KH + 16 * ks + 8 + 2 * q];
                    mma_f16(s[nt], qa[ks], b0, b1);
                }

            if (gt == qt) {
                int rB = rA + 8;
                #pragma unroll
                for (int nt = 0; nt < 8; nt++) {
                    int c0 = 8 * nt + 2 * q;
                    if (c0     > rA) s[nt][0] = -1e30f;
                    if (c0 + 1 > rA) s[nt][1] = -1e30f;
                    if (c0     > rB) s[nt][2] = -1e30f;
                    if (c0 + 1 > rB) s[nt][3] = -1e30f;
                }
            }

            float pm0 = -1e30f, pm1 = -1e30f;
            #pragma unroll
            for (int nt = 0; nt < 8; nt++) {
                pm0 = fmaxf(pm0, fmaxf(s[nt][0], s[nt][1]));
                pm1 = fmaxf(pm1, fmaxf(s[nt][2], s[nt][3]));
            }
            pm0 = fmaxf(pm0, __shfl_xor_sync(~0u, pm0, 1));
            pm0 = fmaxf(pm0, __shfl_xor_sync(~0u, pm0, 2));
            pm1 = fmaxf(pm1, __shfl_xor_sync(~0u, pm1, 1));
            pm1 = fmaxf(pm1, __shfl_xor_sync(~0u, pm1, 2));
            float mn0 = fmaxf(m0r, pm0), mn1 = fmaxf(m1r, pm1);
            float c0f = __expf(m0r - mn0), c1f = __expf(m1r - mn1);
            m0r = mn0; m1r = mn1;
            float su0 = 0.f, su1 = 0.f;
            #pragma unroll
            for (int nt = 0; nt < 8; nt++) {
                s[nt][0] = __expf(s[nt][0] - m0r);
                s[nt][1] = __expf(s[nt][1] - m0r);
                s[nt][2] = __expf(s[nt][2] - m1r);
                s[nt][3] = __expf(s[nt][3] - m1r);
                su0 += s[nt][0] + s[nt][1];
                su1 += s[nt][2] + s[nt][3];
            }
            su0 += __shfl_xor_sync(~0u, su0, 1);
            su0 += __shfl_xor_sync(~0u, su0, 2);
            su1 += __shfl_xor_sync(~0u, su1, 1);
            su1 += __shfl_xor_sync(~0u, su1, 2);
            l0r = l0r * c0f + su0;  l1r = l1r * c1f + su1;
            #pragma unroll
            for (int nt = 0; nt < 8; nt++) {
                o[nt][0] *= c0f; o[nt][1] *= c0f;
                o[nt][2] *= c1f; o[nt][3] *= c1f;
            }
            #pragma unroll
            for (int t = 0; t < 4; t++) {
                uint32_t pa[4];
                pa[0] = packh2(s[2 * t][0],     s[2 * t][1]);
                pa[1] = packh2(s[2 * t][2],     s[2 * t][3]);
                pa[2] = packh2(s[2 * t + 1][0], s[2 * t + 1][1]);
                pa[3] = packh2(s[2 * t + 1][2], s[2 * t + 1][3]);
                #pragma unroll
                for (int nt = 0; nt < 8; nt++) {
                    uint32_t b0 = *(const uint32_t*)&VD[(8 * nt + r) * KH + 16 * t + 2 * q];
                    uint32_t b1 = *(const uint32_t*)&VD[(8 * nt + r) * KH + 16 * t + 8 + 2 * q];
                    mma_f16(o[nt], pa, b0, b1);
                }
            }
        }
    }

    // merge groups
    __syncthreads();
    if (q == 0) {
        mlb[g * 64 + rA]           = m0r;
        mlb[g * 64 + rA + 8]       = m1r;
        mlb[128 + g * 64 + rA]     = l0r;
        mlb[128 + g * 64 + rA + 8] = l1r;
    }
    __syncthreads();
    int og = 1 - g;
    float mo0 = mlb[og * 64 + rA],       mo1 = mlb[og * 64 + rA + 8];
    float lo0 = mlb[128 + og * 64 + rA], lo1 = mlb[128 + og * 64 + rA + 8];
    float M0 = fmaxf(m0r, mo0), M1 = fmaxf(m1r, mo1);
    float sc0 = __expf(m0r - M0), sc1 = __expf(m1r - M1);
    float L0 = l0r * sc0 + lo0 * __expf(mo0 - M0);
    float L1 = l1r * sc1 + lo1 * __expf(mo1 - M1);
    __syncthreads();
    if (g == 1) {
        #pragma unroll
        for (int nt = 0; nt < 8; nt++) {
            int cc = 8 * nt + 2 * q;
            *(float2*)&Of[rA * OSTR + cc] =
                make_float2(o[nt][0] * sc0, o[nt][1] * sc0);
            *(float2*)&Of[(rA + 8) * OSTR + cc] =
                make_float2(o[nt][2] * sc1, o[nt][3] * sc1);
        }
    }
    __syncthreads();
    if (g == 0) {
        if (nc == 1) {   // single chunk: write final result directly
            float* ob = out + (size_t)(b * SS + q0) * DD;
            float i0 = 1.f / L0, i1 = 1.f / L1;
            #pragma unroll
            for (int nt = 0; nt < 8; nt++) {
                int cc = 8 * nt + 2 * q;
                float2 s0 = *(float2*)&Of[rA * OSTR + cc];
                float2 s1 = *(float2*)&Of[(rA + 8) * OSTR + cc];
                *(float2*)&ob[(size_t)rA * DD + cc] = make_float2(
                    (o[nt][0] * sc0 + s0.x) * i0, (o[nt][1] * sc0 + s0.y) * i0);
                *(float2*)&ob[(size_t)(rA + 8) * DD + cc] = make_float2(
                    (o[nt][2] * sc1 + s1.x) * i1, (o[nt][3] * sc1 + s1.y) * i1);
            }
        } else {
            size_t pb = (size_t)(b * 32 + qt) * 8 + ck;
            float* op = &g_part[pb * 4096];
            #pragma unroll
            for (int nt = 0; nt < 8; nt++) {
                int cc = 8 * nt + 2 * q;
                float2 s0 = *(float2*)&Of[rA * OSTR + cc];
                float2 s1 = *(float2*)&Of[(rA + 8) * OSTR + cc];
                *(float2*)&op[rA * 64 + cc] =
                    make_float2(o[nt][0] * sc0 + s0.x, o[nt][1] * sc0 + s0.y);
                *(float2*)&op[(rA + 8) * 64 + cc] =
                    make_float2(o[nt][2] * sc1 + s1.x, o[nt][3] * sc1 + s1.y);
            }
            if (q == 0) {
                float* mp = &g_ml[pb * 128];
                mp[rA] = M0;  mp[rA + 8] = M1;
                mp[64 + rA] = L0;  mp[64 + rA + 8] = L1;
            }
        }
    }
}

// ---------------- flash phase B: one warp per row ----------------
__global__ __launch_bounds__(256) void flash_merge(float* __restrict__ out)
{
    const int gr = blockIdx.x * 8 + (threadIdx.x >> 5);
    const int lane = threadIdx.x & 31;
    const int b = gr >> 11, s = gr & (SS - 1), qt = s >> 6;
    const int nc = (qt + 4) >> 2;
    if (nc < 2) return;   // handled directly by flash_part
    const int row = s & 63;
    const size_t pb = (size_t)(b * 32 + qt) * 8;

    float mv[8], lv[8], M = -1e30f;
    for (int c = 0; c < nc; c++) {
        mv[c] = g_ml[(pb + c) * 128 + row];
        lv[c] = g_ml[(pb + c) * 128 + 64 + row];
        M = fmaxf(M, mv[c]);
    }
    float L = 0.f;
    float2 acc = make_float2(0.f, 0.f);
    for (int c = 0; c < nc; c++) {
        float w = __expf(mv[c] - M);
        L += lv[c] * w;
        float2 v = *(const float2*)&g_part[(pb + c) * 4096 + row * 64 + lane * 2];
        acc.x += w * v.x;  acc.y += w * v.y;
    }
    float inv = 1.f / L;
    *(float2*)&out[(size_t)gr * DD + lane * 2] =
        make_float2(acc.x * inv, acc.y * inv);
}

extern "C" void kernel_launch(void* const* d_in, const int* in_sizes, int n_in,
                              void* d_out, int out_size)
{
    const float* x  = (const float*)d_in[0];
    const float* Wq = (const float*)d_in[2];
    const float* bq = (const float*)d_in[3];
    const float* Wk = (const float*)d_in[4];
    const float* bk = (const float*)d_in[5];
    const float* Wv = (const float*)d_in[6];
    const float* bv = (const float*)d_in[7];
    float* out = (float*)d_out;

    cudaFuncSetAttribute(flash_part,
                         cudaFuncAttributeMaxDynamicSharedMemorySize, SM_PART);
    wcvt<<<dim3(16, 3), 256>>>(Wq, Wk, Wv);
    proj_f16<<<BB * SS / 64, 256>>>(x, bq, bk, bv);
    flash_part<<<dim3(8, 32, BB), 256, SM_PART>>>(out);
    flash_merge<<<BB * SS / 8, 256>>>(out);
}